// round 5
// baseline (speedup 1.0000x reference)
#include <cuda_runtime.h>
#include <cuda_bf16.h>
#include <math.h>
#include <stdint.h>

// ---------------------------------------------------------------------------
// CausalSelfAttention (B=2,T=2048,C=1024,H=16,HD=64)
// R4: dense GEMMs on warp-level mma.sync bf16 (hi/lo split, fp32 accumulate).
//     (tcgen05 rejected by this build's ptxas target sm_103 — no 'a' feature.)
// Flash attention still fp32 (next round's target).
// ---------------------------------------------------------------------------

#define BATCH 2
#define SEQ   2048
#define CH    1024
#define NHEAD 16
#define HDIM  64
#define NROW  (BATCH * SEQ)          // 4096

// ---------------- scratch (static device arrays) ----------------
__device__ float d_qkv[NROW * 3 * CH];
__device__ float d_Qh[NROW * CH];
__device__ float d_Kh[NROW * CH];
__device__ float d_Vh[NROW * CH];
__device__ float d_attn[NROW * CH];

__device__ __nv_bfloat16 d_xhi[NROW * CH];
__device__ __nv_bfloat16 d_xlo[NROW * CH];
__device__ __nv_bfloat16 d_ahi[NROW * CH];
__device__ __nv_bfloat16 d_alo[NROW * CH];
__device__ __nv_bfloat16 d_wahiT[3 * CH * CH];   // [N=3072][K=1024]
__device__ __nv_bfloat16 d_waloT[3 * CH * CH];
__device__ __nv_bfloat16 d_wphiT[CH * CH];       // [N=1024][K=1024]
__device__ __nv_bfloat16 d_wploT[CH * CH];

// ---------------- helpers ----------------
__device__ __forceinline__ uint32_t smem_u32(const void* p) {
    uint32_t a;
    asm("{ .reg .u64 t; cvta.to.shared.u64 t, %1; cvt.u32.u64 %0, t; }"
        : "=r"(a) : "l"(p));
    return a;
}

#define CP_ASYNC16(dst_u32, src_ptr) \
    asm volatile("cp.async.cg.shared.global [%0], [%1], 16;" \
                 :: "r"(dst_u32), "l"(src_ptr) : "memory")
#define CP_COMMIT() asm volatile("cp.async.commit_group;" ::: "memory")
#define CP_WAIT(n)  asm volatile("cp.async.wait_group %0;" :: "n"(n) : "memory")

__device__ __forceinline__ void mma_bf16(float c[4], uint32_t a0, uint32_t a1,
                                         uint32_t a2, uint32_t a3,
                                         uint32_t b0, uint32_t b1) {
    asm volatile(
        "mma.sync.aligned.m16n8k16.row.col.f32.bf16.bf16.f32 "
        "{%0,%1,%2,%3}, {%4,%5,%6,%7}, {%8,%9}, {%0,%1,%2,%3};"
        : "+f"(c[0]), "+f"(c[1]), "+f"(c[2]), "+f"(c[3])
        : "r"(a0), "r"(a1), "r"(a2), "r"(a3), "r"(b0), "r"(b1));
}

// ---------------------------------------------------------------------------
// mma.sync GEMM: C[M,N] = (Ahi+Alo)[M,K] @ (Bhi+Blo)[N,K]^T + bias
// 128x128 tile, BK=32, 256 threads (8 warps as 2x4), warp tile 64x32.
// SMEM padded stride 40 bf16 -> conflict-free direct fragment loads.
// Double-buffered cp.async pipeline.
// ---------------------------------------------------------------------------
#define GM_BK 32
#define GM_AS 40                                  // smem stride (bf16)
#define GM_BUF  (128 * GM_AS)                     // bf16 per matrix buffer
#define GM_STAGE (4 * GM_BUF)                     // Ahi,Alo,Bhi,Blo
#define GM_SMEM_BYTES (2 * GM_STAGE * 2)          // 2 stages * bytes

__global__ __launch_bounds__(256, 2)
void gemm_mma(const __nv_bfloat16* __restrict__ Ahi,
              const __nv_bfloat16* __restrict__ Alo,
              const __nv_bfloat16* __restrict__ Bhi,
              const __nv_bfloat16* __restrict__ Blo,
              const float* __restrict__ bias, float* __restrict__ C,
              int M, int N, int K)
{
    extern __shared__ __nv_bfloat16 sm[];
    const int tid = threadIdx.x;
    const int wid = tid >> 5;
    const int lid = tid & 31;
    const int gid = lid >> 2;       // 0..7
    const int tig = lid & 3;        // 0..3
    const int wm  = (wid >> 2) * 64;    // warp M offset in tile
    const int wn  = (wid & 3) * 32;     // warp N offset in tile
    const int m0  = blockIdx.y * 128;
    const int n0  = blockIdx.x * 128;

    const uint32_t smb = smem_u32(sm);

    // per-thread cp.async chunk assignments: 2048 16B chunks per stage
    // chunk id -> buffer (0..3), row (0..127), k-chunk (0..3)
    float c[4][4][4];
#pragma unroll
    for (int i = 0; i < 4; i++)
#pragma unroll
        for (int j = 0; j < 4; j++)
#pragma unroll
            for (int q = 0; q < 4; q++) c[i][j][q] = 0.f;

    const int KT = K / GM_BK;

    auto issue_stage = [&](int st, int kt) {
        const uint32_t base = smb + (uint32_t)st * (GM_STAGE * 2);
#pragma unroll
        for (int i = 0; i < 8; i++) {
            int id  = tid + i * 256;            // 0..2047
            int buf = id >> 9;                  // 0..3
            int cc  = id & 511;
            int r   = cc >> 2;                  // 0..127
            int kc  = (cc & 3) * 8;             // bf16 within BK
            uint32_t dst = base + (uint32_t)buf * (GM_BUF * 2)
                         + (uint32_t)(r * GM_AS + kc) * 2;
            const __nv_bfloat16* src;
            if (buf == 0)      src = Ahi + (size_t)(m0 + r) * K + kt + kc;
            else if (buf == 1) src = Alo + (size_t)(m0 + r) * K + kt + kc;
            else if (buf == 2) src = Bhi + (size_t)(n0 + r) * K + kt + kc;
            else               src = Blo + (size_t)(n0 + r) * K + kt + kc;
            CP_ASYNC16(dst, src);
        }
        CP_COMMIT();
    };

    issue_stage(0, 0);

    for (int it = 0; it < KT; it++) {
        if (it + 1 < KT) {
            issue_stage((it + 1) & 1, (it + 1) * GM_BK);
            CP_WAIT(1);
        } else {
            CP_WAIT(0);
        }
        __syncthreads();

        const __nv_bfloat16* st = sm + (it & 1) * GM_STAGE;
        const __nv_bfloat16* sAhi = st;
        const __nv_bfloat16* sAlo = st + GM_BUF;
        const __nv_bfloat16* sBhi = st + 2 * GM_BUF;
        const __nv_bfloat16* sBlo = st + 3 * GM_BUF;

#pragma unroll
        for (int ks = 0; ks < GM_BK / 16; ks++) {
            const int kb = ks * 16 + tig * 2;
            uint32_t ah[4][4], al[4][4];
#pragma unroll
            for (int mt = 0; mt < 4; mt++) {
                const int ra = wm + mt * 16 + gid;
                const __nv_bfloat16* p = sAhi + ra * GM_AS + kb;
                ah[mt][0] = *(const uint32_t*)(p);
                ah[mt][1] = *(const uint32_t*)(p + 8 * GM_AS);
                ah[mt][2] = *(const uint32_t*)(p + 8);
                ah[mt][3] = *(const uint32_t*)(p + 8 * GM_AS + 8);
                const __nv_bfloat16* q = sAlo + ra * GM_AS + kb;
                al[mt][0] = *(const uint32_t*)(q);
                al[mt][1] = *(const uint32_t*)(q + 8 * GM_AS);
                al[mt][2] = *(const uint32_t*)(q + 8);
                al[mt][3] = *(const uint32_t*)(q + 8 * GM_AS + 8);
            }
#pragma unroll
            for (int nt = 0; nt < 4; nt++) {
                const int rb = wn + nt * 8 + gid;
                const __nv_bfloat16* p = sBhi + rb * GM_AS + kb;
                uint32_t bh0 = *(const uint32_t*)(p);
                uint32_t bh1 = *(const uint32_t*)(p + 8);
                const __nv_bfloat16* q = sBlo + rb * GM_AS + kb;
                uint32_t bl0 = *(const uint32_t*)(q);
                uint32_t bl1 = *(const uint32_t*)(q + 8);
#pragma unroll
                for (int mt = 0; mt < 4; mt++) {
                    mma_bf16(c[mt][nt], ah[mt][0], ah[mt][1], ah[mt][2], ah[mt][3], bh0, bh1);
                    mma_bf16(c[mt][nt], ah[mt][0], ah[mt][1], ah[mt][2], ah[mt][3], bl0, bl1);
                    mma_bf16(c[mt][nt], al[mt][0], al[mt][1], al[mt][2], al[mt][3], bh0, bh1);
                }
            }
        }
        __syncthreads();
    }

    // epilogue: c[mt][nt] frag (row=gid(+8), col=tig*2(+1)) + bias
#pragma unroll
    for (int mt = 0; mt < 4; mt++) {
#pragma unroll
        for (int nt = 0; nt < 4; nt++) {
            const int row = m0 + wm + mt * 16 + gid;
            const int col = n0 + wn + nt * 8 + tig * 2;
            float2 b01 = *(const float2*)(bias + col);
            float2 v0 = make_float2(c[mt][nt][0] + b01.x, c[mt][nt][1] + b01.y);
            float2 v1 = make_float2(c[mt][nt][2] + b01.x, c[mt][nt][3] + b01.y);
            *(float2*)(C + (size_t)row * N + col)       = v0;
            *(float2*)(C + (size_t)(row + 8) * N + col) = v1;
        }
    }
}

// ---------------------------------------------------------------------------
// elementwise fp32 -> bf16 hi/lo split
// ---------------------------------------------------------------------------
__global__ void split_bf16(const float* __restrict__ X,
                           __nv_bfloat16* __restrict__ hi,
                           __nv_bfloat16* __restrict__ lo, int n)
{
    int i = (blockIdx.x * blockDim.x + threadIdx.x) * 4;
    if (i >= n) return;
    float4 v = *(const float4*)(X + i);
    __nv_bfloat16 h0 = __float2bfloat16(v.x);
    __nv_bfloat16 h1 = __float2bfloat16(v.y);
    __nv_bfloat16 h2 = __float2bfloat16(v.z);
    __nv_bfloat16 h3 = __float2bfloat16(v.w);
    __nv_bfloat162 H01; H01.x = h0; H01.y = h1;
    __nv_bfloat162 H23; H23.x = h2; H23.y = h3;
    *(__nv_bfloat162*)(hi + i)     = H01;
    *(__nv_bfloat162*)(hi + i + 2) = H23;
    __nv_bfloat162 L01, L23;
    L01.x = __float2bfloat16(v.x - __bfloat162float(h0));
    L01.y = __float2bfloat16(v.y - __bfloat162float(h1));
    L23.x = __float2bfloat16(v.z - __bfloat162float(h2));
    L23.y = __float2bfloat16(v.w - __bfloat162float(h3));
    *(__nv_bfloat162*)(lo + i)     = L01;
    *(__nv_bfloat162*)(lo + i + 2) = L23;
}

// ---------------------------------------------------------------------------
// transpose + split: W[K,N] fp32 -> Thi/Tlo[N,K] bf16
// ---------------------------------------------------------------------------
__global__ void transpose_split(const float* __restrict__ W,
                                __nv_bfloat16* __restrict__ Thi,
                                __nv_bfloat16* __restrict__ Tlo,
                                int K, int N)
{
    __shared__ float tile[32][33];
    const int n0 = blockIdx.x * 32;
    const int k0 = blockIdx.y * 32;
    const int tx = threadIdx.x;
    const int ty = threadIdx.y;
#pragma unroll
    for (int i = 0; i < 32; i += 8)
        tile[ty + i][tx] = W[(size_t)(k0 + ty + i) * N + n0 + tx];
    __syncthreads();
#pragma unroll
    for (int i = 0; i < 32; i += 8) {
        float v = tile[tx][ty + i];
        __nv_bfloat16 h = __float2bfloat16(v);
        size_t o = (size_t)(n0 + ty + i) * K + k0 + tx;
        Thi[o] = h;
        Tlo[o] = __float2bfloat16(v - __bfloat162float(h));
    }
}

// ---------------------------------------------------------------------------
// RoPE + head split
// ---------------------------------------------------------------------------
__global__ void rope_split(const float* __restrict__ qkv,
                           const float* __restrict__ cosT,
                           const float* __restrict__ sinT)
{
    int idx = blockIdx.x * blockDim.x + threadIdx.x;
    if (idx >= NROW * (CH / 2)) return;
    int p = idx & 511;
    int n = idx >> 9;
    int t = n & (SEQ - 1);
    int b = n >> 11;
    int h  = p >> 5;
    int pr = p & 31;
    int d0 = pr * 2;

    float c = cosT[t * 32 + pr];
    float s = sinT[t * 32 + pr];

    const float* row = qkv + (size_t)n * (3 * CH);
    float2 q = *(const float2*)(row + p * 2);
    float2 k = *(const float2*)(row + CH + p * 2);
    float2 v = *(const float2*)(row + 2 * CH + p * 2);

    size_t o = ((size_t)(b * NHEAD + h) * SEQ + t) * HDIM + d0;
    *(float2*)(d_Qh + o) = make_float2(q.x * c - q.y * s, q.x * s + q.y * c);
    *(float2*)(d_Kh + o) = make_float2(k.x * c - k.y * s, k.x * s + k.y * c);
    *(float2*)(d_Vh + o) = v;
}

// ---------------------------------------------------------------------------
// Flash attention fp32 (unchanged from R1)
// ---------------------------------------------------------------------------
#define FL_STR 68
#define FL_SMEM_FLOATS (64 * FL_STR * 2 + 64 * 64)
#define FL_SMEM_BYTES  (FL_SMEM_FLOATS * 4)

__global__ __launch_bounds__(256)
void flash_attn(const float* __restrict__ Q, const float* __restrict__ K,
                const float* __restrict__ V, float* __restrict__ Y)
{
    extern __shared__ float smf[];
    float* Qs = smf;
    float* KP = smf + 64 * FL_STR;
    float* Vs = smf + 2 * 64 * FL_STR;

    const int tid = threadIdx.x;
    const int tx  = tid & 15;
    const int ty  = tid >> 4;
    const int qt  = blockIdx.x;
    const int bh  = blockIdx.y;
    const int q0  = qt * 64;

    const float* Qb = Q + (size_t)bh * SEQ * HDIM;
    const float* Kb = K + (size_t)bh * SEQ * HDIM;
    const float* Vb = V + (size_t)bh * SEQ * HDIM;

#pragma unroll
    for (int it = 0; it < 4; it++) {
        int idx = tid + it * 256;
        int r   = idx >> 4;
        int c4  = (idx & 15) * 4;
        float4 v = *(const float4*)(Qb + (size_t)(q0 + r) * HDIM + c4);
        Qs[(c4 + 0) * FL_STR + r] = v.x;
        Qs[(c4 + 1) * FL_STR + r] = v.y;
        Qs[(c4 + 2) * FL_STR + r] = v.z;
        Qs[(c4 + 3) * FL_STR + r] = v.w;
    }

    float m_i[4], l_i[4], o[4][4];
#pragma unroll
    for (int i = 0; i < 4; i++) {
        m_i[i] = -INFINITY; l_i[i] = 0.f;
#pragma unroll
        for (int j = 0; j < 4; j++) o[i][j] = 0.f;
    }

    const int ntiles = qt + 1;
    for (int jt = 0; jt < ntiles; jt++) {
        const int j0 = jt * 64;
        __syncthreads();

#pragma unroll
        for (int it = 0; it < 4; it++) {
            int idx = tid + it * 256;
            int r   = idx >> 4;
            int c4  = (idx & 15) * 4;
            float4 kv = *(const float4*)(Kb + (size_t)(j0 + r) * HDIM + c4);
            KP[(c4 + 0) * FL_STR + r] = kv.x;
            KP[(c4 + 1) * FL_STR + r] = kv.y;
            KP[(c4 + 2) * FL_STR + r] = kv.z;
            KP[(c4 + 3) * FL_STR + r] = kv.w;
            float4 vv = *(const float4*)(Vb + (size_t)(j0 + r) * HDIM + c4);
            *(float4*)&Vs[r * 64 + c4] = vv;
        }
        __syncthreads();

        float s[4][4];
#pragma unroll
        for (int i = 0; i < 4; i++)
#pragma unroll
            for (int j = 0; j < 4; j++) s[i][j] = 0.f;

#pragma unroll 8
        for (int d = 0; d < 64; d++) {
            float4 a = *(float4*)&Qs[d * FL_STR + ty * 4];
            float4 b = *(float4*)&KP[d * FL_STR + tx * 4];
            float ar[4] = {a.x, a.y, a.z, a.w};
            float br[4] = {b.x, b.y, b.z, b.w};
#pragma unroll
            for (int i = 0; i < 4; i++)
#pragma unroll
                for (int j = 0; j < 4; j++)
                    s[i][j] += ar[i] * br[j];
        }

        const float scale = 0.125f;
#pragma unroll
        for (int i = 0; i < 4; i++)
#pragma unroll
            for (int j = 0; j < 4; j++) s[i][j] *= scale;

        if (jt == qt) {
#pragma unroll
            for (int i = 0; i < 4; i++) {
                int qi = q0 + ty * 4 + i;
#pragma unroll
                for (int j = 0; j < 4; j++) {
                    int kj = j0 + tx * 4 + j;
                    if (kj > qi) s[i][j] = -INFINITY;
                }
            }
        }

        float p[4][4];
#pragma unroll
        for (int i = 0; i < 4; i++) {
            float rmax = fmaxf(fmaxf(s[i][0], s[i][1]), fmaxf(s[i][2], s[i][3]));
#pragma unroll
            for (int mks = 1; mks <= 8; mks <<= 1)
                rmax = fmaxf(rmax, __shfl_xor_sync(0xffffffffu, rmax, mks));
            float mnew = fmaxf(m_i[i], rmax);
            float corr = __expf(m_i[i] - mnew);
            float rsum = 0.f;
#pragma unroll
            for (int j = 0; j < 4; j++) {
                p[i][j] = __expf(s[i][j] - mnew);
                rsum += p[i][j];
            }
#pragma unroll
            for (int mks = 1; mks <= 8; mks <<= 1)
                rsum += __shfl_xor_sync(0xffffffffu, rsum, mks);
            l_i[i] = l_i[i] * corr + rsum;
            m_i[i] = mnew;
#pragma unroll
            for (int j = 0; j < 4; j++) o[i][j] *= corr;
        }

        __syncthreads();

#pragma unroll
        for (int j = 0; j < 4; j++) {
            float4 col = make_float4(p[0][j], p[1][j], p[2][j], p[3][j]);
            *(float4*)&KP[(tx * 4 + j) * FL_STR + ty * 4] = col;
        }
        __syncthreads();

#pragma unroll 8
        for (int k = 0; k < 64; k++) {
            float4 a = *(float4*)&KP[k * FL_STR + ty * 4];
            float4 b = *(float4*)&Vs[k * 64 + tx * 4];
            float ar[4] = {a.x, a.y, a.z, a.w};
            float br[4] = {b.x, b.y, b.z, b.w};
#pragma unroll
            for (int i = 0; i < 4; i++)
#pragma unroll
                for (int j = 0; j < 4; j++)
                    o[i][j] += ar[i] * br[j];
        }
    }

    const int b = bh >> 4;
    const int h = bh & 15;
#pragma unroll
    for (int i = 0; i < 4; i++) {
        float inv = 1.f / l_i[i];
        int qi = q0 + ty * 4 + i;
        float4 v = make_float4(o[i][0] * inv, o[i][1] * inv,
                               o[i][2] * inv, o[i][3] * inv);
        *(float4*)(Y + ((size_t)(b * SEQ + qi)) * CH + h * HDIM + tx * 4) = v;
    }
}

// ---------------------------------------------------------------------------
extern "C" void kernel_launch(void* const* d_in, const int* in_sizes, int n_in,
                              void* d_out, int out_size)
{
    const float* x      = (const float*)d_in[0];
    const float* cosT   = (const float*)d_in[1];
    const float* sinT   = (const float*)d_in[2];
    const float* w_attn = (const float*)d_in[3];
    const float* b_attn = (const float*)d_in[4];
    const float* w_proj = (const float*)d_in[5];
    const float* b_proj = (const float*)d_in[6];
    float* out = (float*)d_out;

    float *qkv, *Qh, *Kh, *Vh, *attn;
    cudaGetSymbolAddress((void**)&qkv,  d_qkv);
    cudaGetSymbolAddress((void**)&Qh,   d_Qh);
    cudaGetSymbolAddress((void**)&Kh,   d_Kh);
    cudaGetSymbolAddress((void**)&Vh,   d_Vh);
    cudaGetSymbolAddress((void**)&attn, d_attn);

    __nv_bfloat16 *xhi, *xlo, *ahi, *alo, *wahi, *walo, *wphi, *wplo;
    cudaGetSymbolAddress((void**)&xhi,  d_xhi);
    cudaGetSymbolAddress((void**)&xlo,  d_xlo);
    cudaGetSymbolAddress((void**)&ahi,  d_ahi);
    cudaGetSymbolAddress((void**)&alo,  d_alo);
    cudaGetSymbolAddress((void**)&wahi, d_wahiT);
    cudaGetSymbolAddress((void**)&walo, d_waloT);
    cudaGetSymbolAddress((void**)&wphi, d_wphiT);
    cudaGetSymbolAddress((void**)&wplo, d_wploT);

    cudaFuncSetAttribute(gemm_mma, cudaFuncAttributeMaxDynamicSharedMemorySize,
                         GM_SMEM_BYTES);
    cudaFuncSetAttribute(flash_attn, cudaFuncAttributeMaxDynamicSharedMemorySize,
                         FL_SMEM_BYTES);

    // 0) conversions
    {
        int n = NROW * CH;
        split_bf16<<<(n / 4 + 255) / 256, 256>>>(x, xhi, xlo, n);
        transpose_split<<<dim3(3 * CH / 32, CH / 32), dim3(32, 8)>>>(
            w_attn, wahi, walo, CH, 3 * CH);
        transpose_split<<<dim3(CH / 32, CH / 32), dim3(32, 8)>>>(
            w_proj, wphi, wplo, CH, CH);
    }

    // 1) QKV GEMM (tensor mma.sync): [4096,3072]
    gemm_mma<<<dim3(3 * CH / 128, NROW / 128), 256, GM_SMEM_BYTES>>>(
        xhi, xlo, wahi, walo, b_attn, qkv, NROW, 3 * CH, CH);

    // 2) RoPE + head split
    {
        int total = NROW * (CH / 2);
        rope_split<<<(total + 255) / 256, 256>>>(qkv, cosT, sinT);
    }

    // 3) flash attention (fp32)
    flash_attn<<<dim3(SEQ / 64, BATCH * NHEAD), 256, FL_SMEM_BYTES>>>(
        Qh, Kh, Vh, attn);

    // 4) split attn, projection GEMM
    {
        int n = NROW * CH;
        split_bf16<<<(n / 4 + 255) / 256, 256>>>(attn, ahi, alo, n);
    }
    gemm_mma<<<dim3(CH / 128, NROW / 128), 256, GM_SMEM_BYTES>>>(
        ahi, alo, wphi, wplo, b_proj, out, NROW, CH, CH);
}

// round 6
// speedup vs baseline: 1.8640x; 1.8640x over previous
#include <cuda_runtime.h>
#include <cuda_bf16.h>
#include <math.h>
#include <stdint.h>

// ---------------------------------------------------------------------------
// CausalSelfAttention (B=2,T=2048,C=1024,H=16,HD=64)
// R6: GEMMs on mma.sync bf16 hi/lo (from R4, verified) + flash attention
//     rewritten on mma.sync bf16 hi/lo with cp.async double buffering.
// ---------------------------------------------------------------------------

#define BATCH 2
#define SEQ   2048
#define CH    1024
#define NHEAD 16
#define HDIM  64
#define NROW  (BATCH * SEQ)          // 4096

// ---------------- scratch ----------------
__device__ float d_qkv[NROW * 3 * CH];

__device__ __nv_bfloat16 d_xhi[NROW * CH];
__device__ __nv_bfloat16 d_xlo[NROW * CH];
__device__ __nv_bfloat16 d_ahi[NROW * CH];
__device__ __nv_bfloat16 d_alo[NROW * CH];
__device__ __nv_bfloat16 d_wahiT[3 * CH * CH];
__device__ __nv_bfloat16 d_waloT[3 * CH * CH];
__device__ __nv_bfloat16 d_wphiT[CH * CH];
__device__ __nv_bfloat16 d_wploT[CH * CH];

// per-head bf16 hi/lo operands, [bh][t][d]
__device__ __nv_bfloat16 d_Qhi[NROW * CH];
__device__ __nv_bfloat16 d_Qlo[NROW * CH];
__device__ __nv_bfloat16 d_Khi[NROW * CH];
__device__ __nv_bfloat16 d_Klo[NROW * CH];
__device__ __nv_bfloat16 d_Vhi[NROW * CH];
__device__ __nv_bfloat16 d_Vlo[NROW * CH];
// V transposed: [bh][d][t]
__device__ __nv_bfloat16 d_VThi[NROW * CH];
__device__ __nv_bfloat16 d_VTlo[NROW * CH];

// ---------------- helpers ----------------
__device__ __forceinline__ uint32_t smem_u32(const void* p) {
    uint32_t a;
    asm("{ .reg .u64 t; cvta.to.shared.u64 t, %1; cvt.u32.u64 %0, t; }"
        : "=r"(a) : "l"(p));
    return a;
}

#define CP_ASYNC16(dst_u32, src_ptr) \
    asm volatile("cp.async.cg.shared.global [%0], [%1], 16;" \
                 :: "r"(dst_u32), "l"(src_ptr) : "memory")
#define CP_COMMIT() asm volatile("cp.async.commit_group;" ::: "memory")
#define CP_WAIT(n)  asm volatile("cp.async.wait_group %0;" :: "n"(n) : "memory")

__device__ __forceinline__ void mma_bf16(float c[4], uint32_t a0, uint32_t a1,
                                         uint32_t a2, uint32_t a3,
                                         uint32_t b0, uint32_t b1) {
    asm volatile(
        "mma.sync.aligned.m16n8k16.row.col.f32.bf16.bf16.f32 "
        "{%0,%1,%2,%3}, {%4,%5,%6,%7}, {%8,%9}, {%0,%1,%2,%3};"
        : "+f"(c[0]), "+f"(c[1]), "+f"(c[2]), "+f"(c[3])
        : "r"(a0), "r"(a1), "r"(a2), "r"(a3), "r"(b0), "r"(b1));
}

__device__ __forceinline__ uint32_t pack2(float a, float b) {
    __nv_bfloat162 h = __floats2bfloat162_rn(a, b);
    return *(uint32_t*)&h;
}

// ---------------------------------------------------------------------------
// mma.sync GEMM (unchanged from R4, verified correct)
// ---------------------------------------------------------------------------
#define GM_BK 32
#define GM_AS 40
#define GM_BUF  (128 * GM_AS)
#define GM_STAGE (4 * GM_BUF)
#define GM_SMEM_BYTES (2 * GM_STAGE * 2)

__global__ __launch_bounds__(256, 2)
void gemm_mma(const __nv_bfloat16* __restrict__ Ahi,
              const __nv_bfloat16* __restrict__ Alo,
              const __nv_bfloat16* __restrict__ Bhi,
              const __nv_bfloat16* __restrict__ Blo,
              const float* __restrict__ bias, float* __restrict__ C,
              int M, int N, int K)
{
    extern __shared__ __nv_bfloat16 sm[];
    const int tid = threadIdx.x;
    const int wid = tid >> 5;
    const int lid = tid & 31;
    const int gid = lid >> 2;
    const int tig = lid & 3;
    const int wm  = (wid >> 2) * 64;
    const int wn  = (wid & 3) * 32;
    const int m0  = blockIdx.y * 128;
    const int n0  = blockIdx.x * 128;

    const uint32_t smb = smem_u32(sm);

    float c[4][4][4];
#pragma unroll
    for (int i = 0; i < 4; i++)
#pragma unroll
        for (int j = 0; j < 4; j++)
#pragma unroll
            for (int q = 0; q < 4; q++) c[i][j][q] = 0.f;

    const int KT = K / GM_BK;

    auto issue_stage = [&](int st, int kt) {
        const uint32_t base = smb + (uint32_t)st * (GM_STAGE * 2);
#pragma unroll
        for (int i = 0; i < 8; i++) {
            int id  = tid + i * 256;
            int buf = id >> 9;
            int cc  = id & 511;
            int r   = cc >> 2;
            int kc  = (cc & 3) * 8;
            uint32_t dst = base + (uint32_t)buf * (GM_BUF * 2)
                         + (uint32_t)(r * GM_AS + kc) * 2;
            const __nv_bfloat16* src;
            if (buf == 0)      src = Ahi + (size_t)(m0 + r) * K + kt + kc;
            else if (buf == 1) src = Alo + (size_t)(m0 + r) * K + kt + kc;
            else if (buf == 2) src = Bhi + (size_t)(n0 + r) * K + kt + kc;
            else               src = Blo + (size_t)(n0 + r) * K + kt + kc;
            CP_ASYNC16(dst, src);
        }
        CP_COMMIT();
    };

    issue_stage(0, 0);

    for (int it = 0; it < KT; it++) {
        if (it + 1 < KT) {
            issue_stage((it + 1) & 1, (it + 1) * GM_BK);
            CP_WAIT(1);
        } else {
            CP_WAIT(0);
        }
        __syncthreads();

        const __nv_bfloat16* st = sm + (it & 1) * GM_STAGE;
        const __nv_bfloat16* sAhi = st;
        const __nv_bfloat16* sAlo = st + GM_BUF;
        const __nv_bfloat16* sBhi = st + 2 * GM_BUF;
        const __nv_bfloat16* sBlo = st + 3 * GM_BUF;

#pragma unroll
        for (int ks = 0; ks < GM_BK / 16; ks++) {
            const int kb = ks * 16 + tig * 2;
            uint32_t ah[4][4], al[4][4];
#pragma unroll
            for (int mt = 0; mt < 4; mt++) {
                const int ra = wm + mt * 16 + gid;
                const __nv_bfloat16* p = sAhi + ra * GM_AS + kb;
                ah[mt][0] = *(const uint32_t*)(p);
                ah[mt][1] = *(const uint32_t*)(p + 8 * GM_AS);
                ah[mt][2] = *(const uint32_t*)(p + 8);
                ah[mt][3] = *(const uint32_t*)(p + 8 * GM_AS + 8);
                const __nv_bfloat16* q = sAlo + ra * GM_AS + kb;
                al[mt][0] = *(const uint32_t*)(q);
                al[mt][1] = *(const uint32_t*)(q + 8 * GM_AS);
                al[mt][2] = *(const uint32_t*)(q + 8);
                al[mt][3] = *(const uint32_t*)(q + 8 * GM_AS + 8);
            }
#pragma unroll
            for (int nt = 0; nt < 4; nt++) {
                const int rb = wn + nt * 8 + gid;
                const __nv_bfloat16* p = sBhi + rb * GM_AS + kb;
                uint32_t bh0 = *(const uint32_t*)(p);
                uint32_t bh1 = *(const uint32_t*)(p + 8);
                const __nv_bfloat16* q = sBlo + rb * GM_AS + kb;
                uint32_t bl0 = *(const uint32_t*)(q);
                uint32_t bl1 = *(const uint32_t*)(q + 8);
#pragma unroll
                for (int mt = 0; mt < 4; mt++) {
                    mma_bf16(c[mt][nt], ah[mt][0], ah[mt][1], ah[mt][2], ah[mt][3], bh0, bh1);
                    mma_bf16(c[mt][nt], ah[mt][0], ah[mt][1], ah[mt][2], ah[mt][3], bl0, bl1);
                    mma_bf16(c[mt][nt], al[mt][0], al[mt][1], al[mt][2], al[mt][3], bh0, bh1);
                }
            }
        }
        __syncthreads();
    }

#pragma unroll
    for (int mt = 0; mt < 4; mt++) {
#pragma unroll
        for (int nt = 0; nt < 4; nt++) {
            const int row = m0 + wm + mt * 16 + gid;
            const int col = n0 + wn + nt * 8 + tig * 2;
            float2 b01 = *(const float2*)(bias + col);
            float2 v0 = make_float2(c[mt][nt][0] + b01.x, c[mt][nt][1] + b01.y);
            float2 v1 = make_float2(c[mt][nt][2] + b01.x, c[mt][nt][3] + b01.y);
            *(float2*)(C + (size_t)row * N + col)       = v0;
            *(float2*)(C + (size_t)(row + 8) * N + col) = v1;
        }
    }
}

// ---------------------------------------------------------------------------
// fp32 -> bf16 hi/lo split (x only)
// ---------------------------------------------------------------------------
__global__ void split_bf16(const float* __restrict__ X,
                           __nv_bfloat16* __restrict__ hi,
                           __nv_bfloat16* __restrict__ lo, int n)
{
    int i = (blockIdx.x * blockDim.x + threadIdx.x) * 4;
    if (i >= n) return;
    float4 v = *(const float4*)(X + i);
    __nv_bfloat16 h0 = __float2bfloat16(v.x);
    __nv_bfloat16 h1 = __float2bfloat16(v.y);
    __nv_bfloat16 h2 = __float2bfloat16(v.z);
    __nv_bfloat16 h3 = __float2bfloat16(v.w);
    __nv_bfloat162 H01; H01.x = h0; H01.y = h1;
    __nv_bfloat162 H23; H23.x = h2; H23.y = h3;
    *(__nv_bfloat162*)(hi + i)     = H01;
    *(__nv_bfloat162*)(hi + i + 2) = H23;
    __nv_bfloat162 L01, L23;
    L01.x = __float2bfloat16(v.x - __bfloat162float(h0));
    L01.y = __float2bfloat16(v.y - __bfloat162float(h1));
    L23.x = __float2bfloat16(v.z - __bfloat162float(h2));
    L23.y = __float2bfloat16(v.w - __bfloat162float(h3));
    *(__nv_bfloat162*)(lo + i)     = L01;
    *(__nv_bfloat162*)(lo + i + 2) = L23;
}

// ---------------------------------------------------------------------------
// transpose + split: W[K,N] fp32 -> Thi/Tlo[N,K] bf16
// ---------------------------------------------------------------------------
__global__ void transpose_split(const float* __restrict__ W,
                                __nv_bfloat16* __restrict__ Thi,
                                __nv_bfloat16* __restrict__ Tlo,
                                int K, int N)
{
    __shared__ float tile[32][33];
    const int n0 = blockIdx.x * 32;
    const int k0 = blockIdx.y * 32;
    const int tx = threadIdx.x;
    const int ty = threadIdx.y;
#pragma unroll
    for (int i = 0; i < 32; i += 8)
        tile[ty + i][tx] = W[(size_t)(k0 + ty + i) * N + n0 + tx];
    __syncthreads();
#pragma unroll
    for (int i = 0; i < 32; i += 8) {
        float v = tile[tx][ty + i];
        __nv_bfloat16 h = __float2bfloat16(v);
        size_t o = (size_t)(n0 + ty + i) * K + k0 + tx;
        Thi[o] = h;
        Tlo[o] = __float2bfloat16(v - __bfloat162float(h));
    }
}

// ---------------------------------------------------------------------------
// RoPE + head split -> bf16 hi/lo Q/K/V in [bh][t][d]
// ---------------------------------------------------------------------------
__global__ void rope_split(const float* __restrict__ qkv,
                           const float* __restrict__ cosT,
                           const float* __restrict__ sinT)
{
    int idx = blockIdx.x * blockDim.x + threadIdx.x;
    if (idx >= NROW * (CH / 2)) return;
    int p = idx & 511;
    int n = idx >> 9;
    int t = n & (SEQ - 1);
    int b = n >> 11;
    int h  = p >> 5;
    int pr = p & 31;
    int d0 = pr * 2;

    float c = cosT[t * 32 + pr];
    float s = sinT[t * 32 + pr];

    const float* row = qkv + (size_t)n * (3 * CH);
    float2 q = *(const float2*)(row + p * 2);
    float2 k = *(const float2*)(row + CH + p * 2);
    float2 v = *(const float2*)(row + 2 * CH + p * 2);

    float qx = q.x * c - q.y * s, qy = q.x * s + q.y * c;
    float kx = k.x * c - k.y * s, ky = k.x * s + k.y * c;

    size_t o = ((size_t)(b * NHEAD + h) * SEQ + t) * HDIM + d0;

    float qxh = __bfloat162float(__float2bfloat16(qx));
    float qyh = __bfloat162float(__float2bfloat16(qy));
    float kxh = __bfloat162float(__float2bfloat16(kx));
    float kyh = __bfloat162float(__float2bfloat16(ky));
    float vxh = __bfloat162float(__float2bfloat16(v.x));
    float vyh = __bfloat162float(__float2bfloat16(v.y));

    *(uint32_t*)(d_Qhi + o) = pack2(qxh, qyh);
    *(uint32_t*)(d_Qlo + o) = pack2(qx - qxh, qy - qyh);
    *(uint32_t*)(d_Khi + o) = pack2(kxh, kyh);
    *(uint32_t*)(d_Klo + o) = pack2(kx - kxh, ky - kyh);
    *(uint32_t*)(d_Vhi + o) = pack2(vxh, vyh);
    *(uint32_t*)(d_Vlo + o) = pack2(v.x - vxh, v.y - vyh);
}

// ---------------------------------------------------------------------------
// V transpose: [bh][t][d] -> [bh][d][t] (both hi and lo)
// ---------------------------------------------------------------------------
__global__ void vtrans()
{
    __shared__ unsigned short th[32][33];
    __shared__ unsigned short tl[32][33];
    const int t0 = blockIdx.x * 32;
    const int dz = blockIdx.y * 32;        // 0 or 32
    const int bh = blockIdx.z;
    const int tx = threadIdx.x;
    const int ty = threadIdx.y;
    const size_t inb = (size_t)bh * SEQ * HDIM;
#pragma unroll
    for (int i = 0; i < 32; i += 8) {
        size_t o = inb + (size_t)(t0 + ty + i) * HDIM + dz + tx;
        th[ty + i][tx] = *(const unsigned short*)(d_Vhi + o);
        tl[ty + i][tx] = *(const unsigned short*)(d_Vlo + o);
    }
    __syncthreads();
    const size_t outb = (size_t)bh * HDIM * SEQ;
#pragma unroll
    for (int i = 0; i < 32; i += 8) {
        size_t o = outb + (size_t)(dz + ty + i) * SEQ + t0 + tx;
        *(unsigned short*)(d_VThi + o) = th[tx][ty + i];
        *(unsigned short*)(d_VTlo + o) = tl[tx][ty + i];
    }
}

// ---------------------------------------------------------------------------
// Flash attention on mma.sync bf16 hi/lo.
// CTA: 64 queries, 128 threads (4 warps, 16 q-rows each). Key tiles of 64.
// smem: Q hi/lo [64][72], double-buffered K hi/lo [64][72] + VT hi/lo [64][72].
// Output: normalized O written as bf16 hi/lo (proj GEMM operands).
// ---------------------------------------------------------------------------
#define FA_STRB 144                         // bytes per smem row (72 bf16)
#define FA_TILEB (64 * FA_STRB)             // 9216 B per buffer
#define FA_QBYTES (2 * FA_TILEB)            // Qhi + Qlo
#define FA_KVSTAGE (4 * FA_TILEB)           // Khi,Klo,VThi,VTlo
#define FA_SMEM_BYTES (FA_QBYTES + 2 * FA_KVSTAGE)   // 92160

__global__ __launch_bounds__(128)
void flash_mma(const __nv_bfloat16* __restrict__ Qhi,
               const __nv_bfloat16* __restrict__ Qlo,
               const __nv_bfloat16* __restrict__ Khi,
               const __nv_bfloat16* __restrict__ Klo,
               const __nv_bfloat16* __restrict__ VThi,
               const __nv_bfloat16* __restrict__ VTlo,
               __nv_bfloat16* __restrict__ Ahi,
               __nv_bfloat16* __restrict__ Alo)
{
    extern __shared__ char smem[];
    const uint32_t smb = smem_u32(smem);
    const int tid = threadIdx.x;
    const int wid = tid >> 5;
    const int lid = tid & 31;
    const int g   = lid >> 2;
    const int t   = lid & 3;
    const int wq  = wid * 16;
    const int qt  = gridDim.x - 1 - blockIdx.x;   // heavy tiles first
    const int bh  = blockIdx.y;
    const int q0  = qt * 64;

    const __nv_bfloat16* Qhib = Qhi + (size_t)bh * SEQ * HDIM;
    const __nv_bfloat16* Qlob = Qlo + (size_t)bh * SEQ * HDIM;
    const __nv_bfloat16* Khib = Khi + (size_t)bh * SEQ * HDIM;
    const __nv_bfloat16* Klob = Klo + (size_t)bh * SEQ * HDIM;
    const __nv_bfloat16* VThb = VThi + (size_t)bh * HDIM * SEQ;
    const __nv_bfloat16* VTlb = VTlo + (size_t)bh * HDIM * SEQ;

    auto issue_kv = [&](int st, int kt) {
#pragma unroll
        for (int i = 0; i < 16; i++) {
            int id  = tid + i * 128;          // 0..2047
            int buf = id >> 9;                // 0..3
            int cc  = id & 511;
            int r   = cc >> 3;                // 0..63
            int c8  = (cc & 7) * 8;           // bf16 offset within 64
            uint32_t dst = smb + FA_QBYTES + (uint32_t)st * FA_KVSTAGE
                         + (uint32_t)buf * FA_TILEB + (uint32_t)(r * FA_STRB + c8 * 2);
            const __nv_bfloat16* src;
            if (buf == 0)      src = Khib + (size_t)(kt + r) * HDIM + c8;
            else if (buf == 1) src = Klob + (size_t)(kt + r) * HDIM + c8;
            else if (buf == 2) src = VThb + (size_t)r * SEQ + kt + c8;
            else               src = VTlb + (size_t)r * SEQ + kt + c8;
            CP_ASYNC16(dst, src);
        }
        CP_COMMIT();
    };

    issue_kv(0, 0);

    // load Q tile (hi/lo) into smem
#pragma unroll
    for (int i = 0; i < 4; i++) {
        int id = tid + i * 128;               // 0..511
        int r  = id >> 3;
        int c8 = (id & 7) * 8;
        uint4 vh = *(const uint4*)(Qhib + (size_t)(q0 + r) * HDIM + c8);
        uint4 vl = *(const uint4*)(Qlob + (size_t)(q0 + r) * HDIM + c8);
        *(uint4*)(smem + r * FA_STRB + c8 * 2) = vh;
        *(uint4*)(smem + FA_TILEB + r * FA_STRB + c8 * 2) = vl;
    }

    float m0 = -INFINITY, m1 = -INFINITY, l0 = 0.f, l1 = 0.f;
    float oc[8][4];
#pragma unroll
    for (int nf = 0; nf < 8; nf++)
#pragma unroll
        for (int cidx = 0; cidx < 4; cidx++) oc[nf][cidx] = 0.f;

    const char* sQh = smem;
    const char* sQl = smem + FA_TILEB;

    for (int jt = 0; jt <= qt; jt++) {
        if (jt < qt) {
            issue_kv((jt + 1) & 1, (jt + 1) * 64);
            CP_WAIT(1);
        } else {
            CP_WAIT(0);
        }
        __syncthreads();

        const char* stg = smem + FA_QBYTES + (jt & 1) * FA_KVSTAGE;
        const char* sKh = stg;
        const char* sKl = stg + FA_TILEB;
        const char* sVh = stg + 2 * FA_TILEB;
        const char* sVl = stg + 3 * FA_TILEB;

        // ---- S = Q @ K^T (3-term) ----
        float sc[8][4];
#pragma unroll
        for (int nf = 0; nf < 8; nf++)
#pragma unroll
            for (int cidx = 0; cidx < 4; cidx++) sc[nf][cidx] = 0.f;

#pragma unroll
        for (int kc = 0; kc < 4; kc++) {
            const int co = kc * 32 + t * 4;           // byte offset of d pair
            const int r0 = (wq + g) * FA_STRB;
            const int r1 = (wq + g + 8) * FA_STRB;
            uint32_t qh0 = *(const uint32_t*)(sQh + r0 + co);
            uint32_t qh1 = *(const uint32_t*)(sQh + r1 + co);
            uint32_t qh2 = *(const uint32_t*)(sQh + r0 + co + 16);
            uint32_t qh3 = *(const uint32_t*)(sQh + r1 + co + 16);
            uint32_t ql0 = *(const uint32_t*)(sQl + r0 + co);
            uint32_t ql1 = *(const uint32_t*)(sQl + r1 + co);
            uint32_t ql2 = *(const uint32_t*)(sQl + r0 + co + 16);
            uint32_t ql3 = *(const uint32_t*)(sQl + r1 + co + 16);
#pragma unroll
            for (int nf = 0; nf < 8; nf++) {
                const int kr = (nf * 8 + g) * FA_STRB;
                uint32_t kh0 = *(const uint32_t*)(sKh + kr + co);
                uint32_t kh1 = *(const uint32_t*)(sKh + kr + co + 16);
                uint32_t kl0 = *(const uint32_t*)(sKl + kr + co);
                uint32_t kl1 = *(const uint32_t*)(sKl + kr + co + 16);
                mma_bf16(sc[nf], qh0, qh1, qh2, qh3, kh0, kh1);
                mma_bf16(sc[nf], qh0, qh1, qh2, qh3, kl0, kl1);
                mma_bf16(sc[nf], ql0, ql1, ql2, ql3, kh0, kh1);
            }
        }

        // scale + causal mask
#pragma unroll
        for (int nf = 0; nf < 8; nf++)
#pragma unroll
            for (int cidx = 0; cidx < 4; cidx++) sc[nf][cidx] *= 0.125f;

        if (jt == qt) {
            const int qg0 = q0 + wq + g;
            const int qg1 = qg0 + 8;
#pragma unroll
            for (int nf = 0; nf < 8; nf++) {
                const int kb = q0 + nf * 8 + t * 2;
                if (kb     > qg0) sc[nf][0] = -INFINITY;
                if (kb + 1 > qg0) sc[nf][1] = -INFINITY;
                if (kb     > qg1) sc[nf][2] = -INFINITY;
                if (kb + 1 > qg1) sc[nf][3] = -INFINITY;
            }
        }

        // ---- online softmax (rows g and g+8, 4-lane groups) ----
        float a0 = -INFINITY, a1 = -INFINITY;
#pragma unroll
        for (int nf = 0; nf < 8; nf++) {
            a0 = fmaxf(a0, fmaxf(sc[nf][0], sc[nf][1]));
            a1 = fmaxf(a1, fmaxf(sc[nf][2], sc[nf][3]));
        }
        a0 = fmaxf(a0, __shfl_xor_sync(0xffffffffu, a0, 1));
        a0 = fmaxf(a0, __shfl_xor_sync(0xffffffffu, a0, 2));
        a1 = fmaxf(a1, __shfl_xor_sync(0xffffffffu, a1, 1));
        a1 = fmaxf(a1, __shfl_xor_sync(0xffffffffu, a1, 2));

        float mn0 = fmaxf(m0, a0), mn1 = fmaxf(m1, a1);
        float cr0 = __expf(m0 - mn0), cr1 = __expf(m1 - mn1);
        float rs0 = 0.f, rs1 = 0.f;
#pragma unroll
        for (int nf = 0; nf < 8; nf++) {
            sc[nf][0] = __expf(sc[nf][0] - mn0);
            sc[nf][1] = __expf(sc[nf][1] - mn0);
            sc[nf][2] = __expf(sc[nf][2] - mn1);
            sc[nf][3] = __expf(sc[nf][3] - mn1);
            rs0 += sc[nf][0] + sc[nf][1];
            rs1 += sc[nf][2] + sc[nf][3];
        }
        rs0 += __shfl_xor_sync(0xffffffffu, rs0, 1);
        rs0 += __shfl_xor_sync(0xffffffffu, rs0, 2);
        rs1 += __shfl_xor_sync(0xffffffffu, rs1, 1);
        rs1 += __shfl_xor_sync(0xffffffffu, rs1, 2);
        l0 = l0 * cr0 + rs0;  m0 = mn0;
        l1 = l1 * cr1 + rs1;  m1 = mn1;
#pragma unroll
        for (int nf = 0; nf < 8; nf++) {
            oc[nf][0] *= cr0; oc[nf][1] *= cr0;
            oc[nf][2] *= cr1; oc[nf][3] *= cr1;
        }

        // ---- O += P @ V (3-term; P packed from registers) ----
#pragma unroll
        for (int kc = 0; kc < 4; kc++) {
            float p00 = sc[2*kc][0],   p01 = sc[2*kc][1];
            float p10 = sc[2*kc][2],   p11 = sc[2*kc][3];
            float p20 = sc[2*kc+1][0], p21 = sc[2*kc+1][1];
            float p30 = sc[2*kc+1][2], p31 = sc[2*kc+1][3];
            uint32_t pah0 = pack2(p00, p01);
            uint32_t pah1 = pack2(p10, p11);
            uint32_t pah2 = pack2(p20, p21);
            uint32_t pah3 = pack2(p30, p31);
            __nv_bfloat162 h;
            *(uint32_t*)&h = pah0;
            uint32_t pal0 = pack2(p00 - __bfloat162float(h.x), p01 - __bfloat162float(h.y));
            *(uint32_t*)&h = pah1;
            uint32_t pal1 = pack2(p10 - __bfloat162float(h.x), p11 - __bfloat162float(h.y));
            *(uint32_t*)&h = pah2;
            uint32_t pal2 = pack2(p20 - __bfloat162float(h.x), p21 - __bfloat162float(h.y));
            *(uint32_t*)&h = pah3;
            uint32_t pal3 = pack2(p30 - __bfloat162float(h.x), p31 - __bfloat162float(h.y));

            const int co2 = kc * 32 + t * 4;      // byte offset of key pair
#pragma unroll
            for (int nf = 0; nf < 8; nf++) {
                const int vr = (nf * 8 + g) * FA_STRB;
                uint32_t vh0 = *(const uint32_t*)(sVh + vr + co2);
                uint32_t vh1 = *(const uint32_t*)(sVh + vr + co2 + 16);
                uint32_t vl0 = *(const uint32_t*)(sVl + vr + co2);
                uint32_t vl1 = *(const uint32_t*)(sVl + vr + co2 + 16);
                mma_bf16(oc[nf], pah0, pah1, pah2, pah3, vh0, vh1);
                mma_bf16(oc[nf], pah0, pah1, pah2, pah3, vl0, vl1);
                mma_bf16(oc[nf], pal0, pal1, pal2, pal3, vh0, vh1);
            }
        }
        __syncthreads();
    }

    // ---- epilogue: normalize + hi/lo split, write proj operands ----
    const int b = bh >> 4;
    const int h = bh & 15;
    const float inv0 = 1.f / l0;
    const float inv1 = 1.f / l1;
    const int row0 = b * SEQ + q0 + wq + g;
    const int row1 = row0 + 8;
#pragma unroll
    for (int nf = 0; nf < 8; nf++) {
        const int col = h * HDIM + nf * 8 + t * 2;
        float y00 = oc[nf][0] * inv0, y01 = oc[nf][1] * inv0;
        float y10 = oc[nf][2] * inv1, y11 = oc[nf][3] * inv1;
        float h00 = __bfloat162float(__float2bfloat16(y00));
        float h01 = __bfloat162float(__float2bfloat16(y01));
        float h10 = __bfloat162float(__float2bfloat16(y10));
        float h11 = __bfloat162float(__float2bfloat16(y11));
        *(uint32_t*)(Ahi + (size_t)row0 * CH + col) = pack2(h00, h01);
        *(uint32_t*)(Alo + (size_t)row0 * CH + col) = pack2(y00 - h00, y01 - h01);
        *(uint32_t*)(Ahi + (size_t)row1 * CH + col) = pack2(h10, h11);
        *(uint32_t*)(Alo + (size_t)row1 * CH + col) = pack2(y10 - h10, y11 - h11);
    }
}

// ---------------------------------------------------------------------------
extern "C" void kernel_launch(void* const* d_in, const int* in_sizes, int n_in,
                              void* d_out, int out_size)
{
    const float* x      = (const float*)d_in[0];
    const float* cosT   = (const float*)d_in[1];
    const float* sinT   = (const float*)d_in[2];
    const float* w_attn = (const float*)d_in[3];
    const float* b_attn = (const float*)d_in[4];
    const float* w_proj = (const float*)d_in[5];
    const float* b_proj = (const float*)d_in[6];
    float* out = (float*)d_out;

    float* qkv;
    cudaGetSymbolAddress((void**)&qkv, d_qkv);

    __nv_bfloat16 *xhi, *xlo, *ahi, *alo, *wahi, *walo, *wphi, *wplo;
    __nv_bfloat16 *qh, *ql, *kh, *kl, *vth, *vtl;
    cudaGetSymbolAddress((void**)&xhi,  d_xhi);
    cudaGetSymbolAddress((void**)&xlo,  d_xlo);
    cudaGetSymbolAddress((void**)&ahi,  d_ahi);
    cudaGetSymbolAddress((void**)&alo,  d_alo);
    cudaGetSymbolAddress((void**)&wahi, d_wahiT);
    cudaGetSymbolAddress((void**)&walo, d_waloT);
    cudaGetSymbolAddress((void**)&wphi, d_wphiT);
    cudaGetSymbolAddress((void**)&wplo, d_wploT);
    cudaGetSymbolAddress((void**)&qh,   d_Qhi);
    cudaGetSymbolAddress((void**)&ql,   d_Qlo);
    cudaGetSymbolAddress((void**)&kh,   d_Khi);
    cudaGetSymbolAddress((void**)&kl,   d_Klo);
    cudaGetSymbolAddress((void**)&vth,  d_VThi);
    cudaGetSymbolAddress((void**)&vtl,  d_VTlo);

    cudaFuncSetAttribute(gemm_mma, cudaFuncAttributeMaxDynamicSharedMemorySize,
                         GM_SMEM_BYTES);
    cudaFuncSetAttribute(flash_mma, cudaFuncAttributeMaxDynamicSharedMemorySize,
                         FA_SMEM_BYTES);

    // 0) conversions
    {
        int n = NROW * CH;
        split_bf16<<<(n / 4 + 255) / 256, 256>>>(x, xhi, xlo, n);
        transpose_split<<<dim3(3 * CH / 32, CH / 32), dim3(32, 8)>>>(
            w_attn, wahi, walo, CH, 3 * CH);
        transpose_split<<<dim3(CH / 32, CH / 32), dim3(32, 8)>>>(
            w_proj, wphi, wplo, CH, CH);
    }

    // 1) QKV GEMM
    gemm_mma<<<dim3(3 * CH / 128, NROW / 128), 256, GM_SMEM_BYTES>>>(
        xhi, xlo, wahi, walo, b_attn, qkv, NROW, 3 * CH, CH);

    // 2) RoPE + head split -> bf16 hi/lo
    {
        int total = NROW * (CH / 2);
        rope_split<<<(total + 255) / 256, 256>>>(qkv, cosT, sinT);
    }

    // 3) V transpose
    vtrans<<<dim3(SEQ / 32, HDIM / 32, BATCH * NHEAD), dim3(32, 8)>>>();

    // 4) flash attention (tensor) -> writes proj operands ahi/alo
    flash_mma<<<dim3(SEQ / 64, BATCH * NHEAD), 128, FA_SMEM_BYTES>>>(
        qh, ql, kh, kl, vth, vtl, ahi, alo);

    // 5) projection GEMM
    gemm_mma<<<dim3(CH / 128, NROW / 128), 256, GM_SMEM_BYTES>>>(
        ahi, alo, wphi, wplo, b_proj, out, NROW, CH, CH);
}

// round 7
// speedup vs baseline: 2.9534x; 1.5845x over previous
#include <cuda_runtime.h>
#include <cuda_bf16.h>
#include <math.h>
#include <stdint.h>

// ---------------------------------------------------------------------------
// CausalSelfAttention (B=2,T=2048,C=1024,H=16,HD=64)
// R7: R6 + ldmatrix fragment loads in both GEMM and flash (LSU was pacing
//     the tensor pipe at 50%).
// ---------------------------------------------------------------------------

#define BATCH 2
#define SEQ   2048
#define CH    1024
#define NHEAD 16
#define HDIM  64
#define NROW  (BATCH * SEQ)

// ---------------- scratch ----------------
__device__ float d_qkv[NROW * 3 * CH];

__device__ __nv_bfloat16 d_xhi[NROW * CH];
__device__ __nv_bfloat16 d_xlo[NROW * CH];
__device__ __nv_bfloat16 d_ahi[NROW * CH];
__device__ __nv_bfloat16 d_alo[NROW * CH];
__device__ __nv_bfloat16 d_wahiT[3 * CH * CH];
__device__ __nv_bfloat16 d_waloT[3 * CH * CH];
__device__ __nv_bfloat16 d_wphiT[CH * CH];
__device__ __nv_bfloat16 d_wploT[CH * CH];

__device__ __nv_bfloat16 d_Qhi[NROW * CH];
__device__ __nv_bfloat16 d_Qlo[NROW * CH];
__device__ __nv_bfloat16 d_Khi[NROW * CH];
__device__ __nv_bfloat16 d_Klo[NROW * CH];
__device__ __nv_bfloat16 d_Vhi[NROW * CH];
__device__ __nv_bfloat16 d_Vlo[NROW * CH];
__device__ __nv_bfloat16 d_VThi[NROW * CH];
__device__ __nv_bfloat16 d_VTlo[NROW * CH];

// ---------------- helpers ----------------
__device__ __forceinline__ uint32_t smem_u32(const void* p) {
    uint32_t a;
    asm("{ .reg .u64 t; cvta.to.shared.u64 t, %1; cvt.u32.u64 %0, t; }"
        : "=r"(a) : "l"(p));
    return a;
}

#define CP_ASYNC16(dst_u32, src_ptr) \
    asm volatile("cp.async.cg.shared.global [%0], [%1], 16;" \
                 :: "r"(dst_u32), "l"(src_ptr) : "memory")
#define CP_COMMIT() asm volatile("cp.async.commit_group;" ::: "memory")
#define CP_WAIT(n)  asm volatile("cp.async.wait_group %0;" :: "n"(n) : "memory")

__device__ __forceinline__ void mma_bf16(float c[4], uint32_t a0, uint32_t a1,
                                         uint32_t a2, uint32_t a3,
                                         uint32_t b0, uint32_t b1) {
    asm volatile(
        "mma.sync.aligned.m16n8k16.row.col.f32.bf16.bf16.f32 "
        "{%0,%1,%2,%3}, {%4,%5,%6,%7}, {%8,%9}, {%0,%1,%2,%3};"
        : "+f"(c[0]), "+f"(c[1]), "+f"(c[2]), "+f"(c[3])
        : "r"(a0), "r"(a1), "r"(a2), "r"(a3), "r"(b0), "r"(b1));
}

__device__ __forceinline__ void ldsm4(uint32_t& r0, uint32_t& r1,
                                      uint32_t& r2, uint32_t& r3, uint32_t a) {
    asm volatile("ldmatrix.sync.aligned.m8n8.x4.shared.b16 {%0,%1,%2,%3}, [%4];"
                 : "=r"(r0), "=r"(r1), "=r"(r2), "=r"(r3) : "r"(a));
}

__device__ __forceinline__ uint32_t pack2(float a, float b) {
    __nv_bfloat162 h = __floats2bfloat162_rn(a, b);
    return *(uint32_t*)&h;
}

// ---------------------------------------------------------------------------
// mma.sync GEMM with ldmatrix fragment loads
// ---------------------------------------------------------------------------
#define GM_BK 32
#define GM_AS 40
#define GM_ROWB (GM_AS * 2)                 // 80 bytes/row
#define GM_BUFB (128 * GM_ROWB)             // bytes per matrix buffer
#define GM_STAGEB (4 * GM_BUFB)
#define GM_SMEM_BYTES (2 * GM_STAGEB)

__global__ __launch_bounds__(256, 2)
void gemm_mma(const __nv_bfloat16* __restrict__ Ahi,
              const __nv_bfloat16* __restrict__ Alo,
              const __nv_bfloat16* __restrict__ Bhi,
              const __nv_bfloat16* __restrict__ Blo,
              const float* __restrict__ bias, float* __restrict__ C,
              int M, int N, int K)
{
    extern __shared__ char sm[];
    const int tid = threadIdx.x;
    const int wid = tid >> 5;
    const int lid = tid & 31;
    const int gid = lid >> 2;
    const int tig = lid & 3;
    const int wm  = (wid >> 2) * 64;
    const int wn  = (wid & 3) * 32;
    const int m0  = blockIdx.y * 128;
    const int n0  = blockIdx.x * 128;

    const uint32_t smb = smem_u32(sm);

    // ldmatrix lane address components
    const int aRow = lid & 15;                 // A: rows 0..15 of 16x16
    const int aCol = (lid >> 4) << 4;          // 0 or 16 bytes (k half)
    const int bRow = (lid & 7) + ((lid & 16) >> 1);   // B: row within 16
    const int bCol = ((lid >> 3) & 1) << 4;    // k half

    float c[4][4][4];
#pragma unroll
    for (int i = 0; i < 4; i++)
#pragma unroll
        for (int j = 0; j < 4; j++)
#pragma unroll
            for (int q = 0; q < 4; q++) c[i][j][q] = 0.f;

    const int KT = K / GM_BK;

    auto issue_stage = [&](int st, int kt) {
        const uint32_t base = smb + (uint32_t)st * GM_STAGEB;
#pragma unroll
        for (int i = 0; i < 8; i++) {
            int id  = tid + i * 256;
            int buf = id >> 9;
            int cc  = id & 511;
            int r   = cc >> 2;
            int kc  = (cc & 3) * 8;
            uint32_t dst = base + (uint32_t)buf * GM_BUFB
                         + (uint32_t)(r * GM_ROWB + kc * 2);
            const __nv_bfloat16* src;
            if (buf == 0)      src = Ahi + (size_t)(m0 + r) * K + kt + kc;
            else if (buf == 1) src = Alo + (size_t)(m0 + r) * K + kt + kc;
            else if (buf == 2) src = Bhi + (size_t)(n0 + r) * K + kt + kc;
            else               src = Blo + (size_t)(n0 + r) * K + kt + kc;
            CP_ASYNC16(dst, src);
        }
        CP_COMMIT();
    };

    issue_stage(0, 0);

    for (int it = 0; it < KT; it++) {
        if (it + 1 < KT) {
            issue_stage((it + 1) & 1, (it + 1) * GM_BK);
            CP_WAIT(1);
        } else {
            CP_WAIT(0);
        }
        __syncthreads();

        const uint32_t stb = smb + (uint32_t)(it & 1) * GM_STAGEB;

#pragma unroll
        for (int ks = 0; ks < GM_BK / 16; ks++) {
            const uint32_t kOff = (uint32_t)(ks * 32);
            uint32_t ah[4][4], al[4][4];
#pragma unroll
            for (int mt = 0; mt < 4; mt++) {
                uint32_t ra = stb + (uint32_t)((wm + mt * 16 + aRow) * GM_ROWB)
                            + kOff + aCol;
                ldsm4(ah[mt][0], ah[mt][1], ah[mt][2], ah[mt][3], ra);
                ldsm4(al[mt][0], al[mt][1], al[mt][2], al[mt][3], ra + GM_BUFB);
            }
            uint32_t bh[4][2], bl[4][2];
#pragma unroll
            for (int p = 0; p < 2; p++) {
                uint32_t rb = stb + 2 * GM_BUFB
                            + (uint32_t)((wn + p * 16 + bRow) * GM_ROWB)
                            + kOff + bCol;
                ldsm4(bh[2*p][0], bh[2*p][1], bh[2*p+1][0], bh[2*p+1][1], rb);
                ldsm4(bl[2*p][0], bl[2*p][1], bl[2*p+1][0], bl[2*p+1][1],
                      rb + GM_BUFB);
            }
#pragma unroll
            for (int nt = 0; nt < 4; nt++)
#pragma unroll
                for (int mt = 0; mt < 4; mt++) {
                    mma_bf16(c[mt][nt], ah[mt][0], ah[mt][1], ah[mt][2], ah[mt][3],
                             bh[nt][0], bh[nt][1]);
                    mma_bf16(c[mt][nt], ah[mt][0], ah[mt][1], ah[mt][2], ah[mt][3],
                             bl[nt][0], bl[nt][1]);
                    mma_bf16(c[mt][nt], al[mt][0], al[mt][1], al[mt][2], al[mt][3],
                             bh[nt][0], bh[nt][1]);
                }
        }
        __syncthreads();
    }

#pragma unroll
    for (int mt = 0; mt < 4; mt++) {
#pragma unroll
        for (int nt = 0; nt < 4; nt++) {
            const int row = m0 + wm + mt * 16 + gid;
            const int col = n0 + wn + nt * 8 + tig * 2;
            float2 b01 = *(const float2*)(bias + col);
            float2 v0 = make_float2(c[mt][nt][0] + b01.x, c[mt][nt][1] + b01.y);
            float2 v1 = make_float2(c[mt][nt][2] + b01.x, c[mt][nt][3] + b01.y);
            *(float2*)(C + (size_t)row * N + col)       = v0;
            *(float2*)(C + (size_t)(row + 8) * N + col) = v1;
        }
    }
}

// ---------------------------------------------------------------------------
// fp32 -> bf16 hi/lo split
// ---------------------------------------------------------------------------
__global__ void split_bf16(const float* __restrict__ X,
                           __nv_bfloat16* __restrict__ hi,
                           __nv_bfloat16* __restrict__ lo, int n)
{
    int i = (blockIdx.x * blockDim.x + threadIdx.x) * 4;
    if (i >= n) return;
    float4 v = *(const float4*)(X + i);
    __nv_bfloat16 h0 = __float2bfloat16(v.x);
    __nv_bfloat16 h1 = __float2bfloat16(v.y);
    __nv_bfloat16 h2 = __float2bfloat16(v.z);
    __nv_bfloat16 h3 = __float2bfloat16(v.w);
    __nv_bfloat162 H01; H01.x = h0; H01.y = h1;
    __nv_bfloat162 H23; H23.x = h2; H23.y = h3;
    *(__nv_bfloat162*)(hi + i)     = H01;
    *(__nv_bfloat162*)(hi + i + 2) = H23;
    __nv_bfloat162 L01, L23;
    L01.x = __float2bfloat16(v.x - __bfloat162float(h0));
    L01.y = __float2bfloat16(v.y - __bfloat162float(h1));
    L23.x = __float2bfloat16(v.z - __bfloat162float(h2));
    L23.y = __float2bfloat16(v.w - __bfloat162float(h3));
    *(__nv_bfloat162*)(lo + i)     = L01;
    *(__nv_bfloat162*)(lo + i + 2) = L23;
}

// ---------------------------------------------------------------------------
// transpose + split: W[K,N] fp32 -> Thi/Tlo[N,K] bf16
// ---------------------------------------------------------------------------
__global__ void transpose_split(const float* __restrict__ W,
                                __nv_bfloat16* __restrict__ Thi,
                                __nv_bfloat16* __restrict__ Tlo,
                                int K, int N)
{
    __shared__ float tile[32][33];
    const int n0 = blockIdx.x * 32;
    const int k0 = blockIdx.y * 32;
    const int tx = threadIdx.x;
    const int ty = threadIdx.y;
#pragma unroll
    for (int i = 0; i < 32; i += 8)
        tile[ty + i][tx] = W[(size_t)(k0 + ty + i) * N + n0 + tx];
    __syncthreads();
#pragma unroll
    for (int i = 0; i < 32; i += 8) {
        float v = tile[tx][ty + i];
        __nv_bfloat16 h = __float2bfloat16(v);
        size_t o = (size_t)(n0 + ty + i) * K + k0 + tx;
        Thi[o] = h;
        Tlo[o] = __float2bfloat16(v - __bfloat162float(h));
    }
}

// ---------------------------------------------------------------------------
// RoPE + head split -> bf16 hi/lo Q/K/V in [bh][t][d]
// ---------------------------------------------------------------------------
__global__ void rope_split(const float* __restrict__ qkv,
                           const float* __restrict__ cosT,
                           const float* __restrict__ sinT)
{
    int idx = blockIdx.x * blockDim.x + threadIdx.x;
    if (idx >= NROW * (CH / 2)) return;
    int p = idx & 511;
    int n = idx >> 9;
    int t = n & (SEQ - 1);
    int b = n >> 11;
    int h  = p >> 5;
    int pr = p & 31;
    int d0 = pr * 2;

    float c = cosT[t * 32 + pr];
    float s = sinT[t * 32 + pr];

    const float* row = qkv + (size_t)n * (3 * CH);
    float2 q = *(const float2*)(row + p * 2);
    float2 k = *(const float2*)(row + CH + p * 2);
    float2 v = *(const float2*)(row + 2 * CH + p * 2);

    float qx = q.x * c - q.y * s, qy = q.x * s + q.y * c;
    float kx = k.x * c - k.y * s, ky = k.x * s + k.y * c;

    size_t o = ((size_t)(b * NHEAD + h) * SEQ + t) * HDIM + d0;

    float qxh = __bfloat162float(__float2bfloat16(qx));
    float qyh = __bfloat162float(__float2bfloat16(qy));
    float kxh = __bfloat162float(__float2bfloat16(kx));
    float kyh = __bfloat162float(__float2bfloat16(ky));
    float vxh = __bfloat162float(__float2bfloat16(v.x));
    float vyh = __bfloat162float(__float2bfloat16(v.y));

    *(uint32_t*)(d_Qhi + o) = pack2(qxh, qyh);
    *(uint32_t*)(d_Qlo + o) = pack2(qx - qxh, qy - qyh);
    *(uint32_t*)(d_Khi + o) = pack2(kxh, kyh);
    *(uint32_t*)(d_Klo + o) = pack2(kx - kxh, ky - kyh);
    *(uint32_t*)(d_Vhi + o) = pack2(vxh, vyh);
    *(uint32_t*)(d_Vlo + o) = pack2(v.x - vxh, v.y - vyh);
}

// ---------------------------------------------------------------------------
// V transpose: [bh][t][d] -> [bh][d][t]
// ---------------------------------------------------------------------------
__global__ void vtrans()
{
    __shared__ unsigned short th[32][33];
    __shared__ unsigned short tl[32][33];
    const int t0 = blockIdx.x * 32;
    const int dz = blockIdx.y * 32;
    const int bh = blockIdx.z;
    const int tx = threadIdx.x;
    const int ty = threadIdx.y;
    const size_t inb = (size_t)bh * SEQ * HDIM;
#pragma unroll
    for (int i = 0; i < 32; i += 8) {
        size_t o = inb + (size_t)(t0 + ty + i) * HDIM + dz + tx;
        th[ty + i][tx] = *(const unsigned short*)(d_Vhi + o);
        tl[ty + i][tx] = *(const unsigned short*)(d_Vlo + o);
    }
    __syncthreads();
    const size_t outb = (size_t)bh * HDIM * SEQ;
#pragma unroll
    for (int i = 0; i < 32; i += 8) {
        size_t o = outb + (size_t)(dz + ty + i) * SEQ + t0 + tx;
        *(unsigned short*)(d_VThi + o) = th[tx][ty + i];
        *(unsigned short*)(d_VTlo + o) = tl[tx][ty + i];
    }
}

// ---------------------------------------------------------------------------
// Flash attention (mma.sync bf16 hi/lo, ldmatrix loads)
// ---------------------------------------------------------------------------
#define FA_STRB 144
#define FA_TILEB (64 * FA_STRB)
#define FA_QBYTES (2 * FA_TILEB)
#define FA_KVSTAGE (4 * FA_TILEB)
#define FA_SMEM_BYTES (FA_QBYTES + 2 * FA_KVSTAGE)

__global__ __launch_bounds__(128)
void flash_mma(const __nv_bfloat16* __restrict__ Qhi,
               const __nv_bfloat16* __restrict__ Qlo,
               const __nv_bfloat16* __restrict__ Khi,
               const __nv_bfloat16* __restrict__ Klo,
               const __nv_bfloat16* __restrict__ VThi,
               const __nv_bfloat16* __restrict__ VTlo,
               __nv_bfloat16* __restrict__ Ahi,
               __nv_bfloat16* __restrict__ Alo)
{
    extern __shared__ char smem[];
    const uint32_t smb = smem_u32(smem);
    const int tid = threadIdx.x;
    const int wid = tid >> 5;
    const int lid = tid & 31;
    const int g   = lid >> 2;
    const int t   = lid & 3;
    const int wq  = wid * 16;
    const int qt  = gridDim.x - 1 - blockIdx.x;
    const int bh  = blockIdx.y;
    const int q0  = qt * 64;

    const int aRow = lid & 15;
    const int aCol = (lid >> 4) << 4;
    const int bRow = (lid & 7) + ((lid & 16) >> 1);
    const int bCol = ((lid >> 3) & 1) << 4;

    const __nv_bfloat16* Qhib = Qhi + (size_t)bh * SEQ * HDIM;
    const __nv_bfloat16* Qlob = Qlo + (size_t)bh * SEQ * HDIM;
    const __nv_bfloat16* Khib = Khi + (size_t)bh * SEQ * HDIM;
    const __nv_bfloat16* Klob = Klo + (size_t)bh * SEQ * HDIM;
    const __nv_bfloat16* VThb = VThi + (size_t)bh * HDIM * SEQ;
    const __nv_bfloat16* VTlb = VTlo + (size_t)bh * HDIM * SEQ;

    auto issue_kv = [&](int st, int kt) {
#pragma unroll
        for (int i = 0; i < 16; i++) {
            int id  = tid + i * 128;
            int buf = id >> 9;
            int cc  = id & 511;
            int r   = cc >> 3;
            int c8  = (cc & 7) * 8;
            uint32_t dst = smb + FA_QBYTES + (uint32_t)st * FA_KVSTAGE
                         + (uint32_t)buf * FA_TILEB + (uint32_t)(r * FA_STRB + c8 * 2);
            const __nv_bfloat16* src;
            if (buf == 0)      src = Khib + (size_t)(kt + r) * HDIM + c8;
            else if (buf == 1) src = Klob + (size_t)(kt + r) * HDIM + c8;
            else if (buf == 2) src = VThb + (size_t)r * SEQ + kt + c8;
            else               src = VTlb + (size_t)r * SEQ + kt + c8;
            CP_ASYNC16(dst, src);
        }
        CP_COMMIT();
    };

    issue_kv(0, 0);

#pragma unroll
    for (int i = 0; i < 4; i++) {
        int id = tid + i * 128;
        int r  = id >> 3;
        int c8 = (id & 7) * 8;
        uint4 vh = *(const uint4*)(Qhib + (size_t)(q0 + r) * HDIM + c8);
        uint4 vl = *(const uint4*)(Qlob + (size_t)(q0 + r) * HDIM + c8);
        *(uint4*)(smem + r * FA_STRB + c8 * 2) = vh;
        *(uint4*)(smem + FA_TILEB + r * FA_STRB + c8 * 2) = vl;
    }

    float m0 = -INFINITY, m1 = -INFINITY, l0 = 0.f, l1 = 0.f;
    float oc[8][4];
#pragma unroll
    for (int nf = 0; nf < 8; nf++)
#pragma unroll
        for (int cidx = 0; cidx < 4; cidx++) oc[nf][cidx] = 0.f;

    for (int jt = 0; jt <= qt; jt++) {
        if (jt < qt) {
            issue_kv((jt + 1) & 1, (jt + 1) * 64);
            CP_WAIT(1);
        } else {
            CP_WAIT(0);
        }
        __syncthreads();

        const uint32_t kvb = smb + FA_QBYTES + (uint32_t)(jt & 1) * FA_KVSTAGE;

        // ---- S = Q @ K^T (3-term) ----
        float sc[8][4];
#pragma unroll
        for (int nf = 0; nf < 8; nf++)
#pragma unroll
            for (int cidx = 0; cidx < 4; cidx++) sc[nf][cidx] = 0.f;

#pragma unroll
        for (int kc = 0; kc < 4; kc++) {
            const uint32_t kOff = (uint32_t)(kc * 32);
            uint32_t qh[4], ql[4];
            uint32_t qa = smb + (uint32_t)((wq + aRow) * FA_STRB) + kOff + aCol;
            ldsm4(qh[0], qh[1], qh[2], qh[3], qa);
            ldsm4(ql[0], ql[1], ql[2], ql[3], qa + FA_TILEB);
#pragma unroll
            for (int p = 0; p < 4; p++) {
                uint32_t ka = kvb + (uint32_t)((p * 16 + bRow) * FA_STRB)
                            + kOff + bCol;
                uint32_t kh0, kh1, kh2, kh3, kl0, kl1, kl2, kl3;
                ldsm4(kh0, kh1, kh2, kh3, ka);
                ldsm4(kl0, kl1, kl2, kl3, ka + FA_TILEB);
                mma_bf16(sc[2*p],   qh[0], qh[1], qh[2], qh[3], kh0, kh1);
                mma_bf16(sc[2*p],   qh[0], qh[1], qh[2], qh[3], kl0, kl1);
                mma_bf16(sc[2*p],   ql[0], ql[1], ql[2], ql[3], kh0, kh1);
                mma_bf16(sc[2*p+1], qh[0], qh[1], qh[2], qh[3], kh2, kh3);
                mma_bf16(sc[2*p+1], qh[0], qh[1], qh[2], qh[3], kl2, kl3);
                mma_bf16(sc[2*p+1], ql[0], ql[1], ql[2], ql[3], kh2, kh3);
            }
        }

#pragma unroll
        for (int nf = 0; nf < 8; nf++)
#pragma unroll
            for (int cidx = 0; cidx < 4; cidx++) sc[nf][cidx] *= 0.125f;

        if (jt == qt) {
            const int qg0 = q0 + wq + g;
            const int qg1 = qg0 + 8;
#pragma unroll
            for (int nf = 0; nf < 8; nf++) {
                const int kb = q0 + nf * 8 + t * 2;
                if (kb     > qg0) sc[nf][0] = -INFINITY;
                if (kb + 1 > qg0) sc[nf][1] = -INFINITY;
                if (kb     > qg1) sc[nf][2] = -INFINITY;
                if (kb + 1 > qg1) sc[nf][3] = -INFINITY;
            }
        }

        // ---- online softmax ----
        float a0 = -INFINITY, a1 = -INFINITY;
#pragma unroll
        for (int nf = 0; nf < 8; nf++) {
            a0 = fmaxf(a0, fmaxf(sc[nf][0], sc[nf][1]));
            a1 = fmaxf(a1, fmaxf(sc[nf][2], sc[nf][3]));
        }
        a0 = fmaxf(a0, __shfl_xor_sync(0xffffffffu, a0, 1));
        a0 = fmaxf(a0, __shfl_xor_sync(0xffffffffu, a0, 2));
        a1 = fmaxf(a1, __shfl_xor_sync(0xffffffffu, a1, 1));
        a1 = fmaxf(a1, __shfl_xor_sync(0xffffffffu, a1, 2));

        float mn0 = fmaxf(m0, a0), mn1 = fmaxf(m1, a1);
        float cr0 = __expf(m0 - mn0), cr1 = __expf(m1 - mn1);
        float rs0 = 0.f, rs1 = 0.f;
#pragma unroll
        for (int nf = 0; nf < 8; nf++) {
            sc[nf][0] = __expf(sc[nf][0] - mn0);
            sc[nf][1] = __expf(sc[nf][1] - mn0);
            sc[nf][2] = __expf(sc[nf][2] - mn1);
            sc[nf][3] = __expf(sc[nf][3] - mn1);
            rs0 += sc[nf][0] + sc[nf][1];
            rs1 += sc[nf][2] + sc[nf][3];
        }
        rs0 += __shfl_xor_sync(0xffffffffu, rs0, 1);
        rs0 += __shfl_xor_sync(0xffffffffu, rs0, 2);
        rs1 += __shfl_xor_sync(0xffffffffu, rs1, 1);
        rs1 += __shfl_xor_sync(0xffffffffu, rs1, 2);
        l0 = l0 * cr0 + rs0;  m0 = mn0;
        l1 = l1 * cr1 + rs1;  m1 = mn1;
#pragma unroll
        for (int nf = 0; nf < 8; nf++) {
            oc[nf][0] *= cr0; oc[nf][1] *= cr0;
            oc[nf][2] *= cr1; oc[nf][3] *= cr1;
        }

        // ---- O += P @ V (3-term) ----
#pragma unroll
        for (int kc = 0; kc < 4; kc++) {
            float p00 = sc[2*kc][0],   p01 = sc[2*kc][1];
            float p10 = sc[2*kc][2],   p11 = sc[2*kc][3];
            float p20 = sc[2*kc+1][0], p21 = sc[2*kc+1][1];
            float p30 = sc[2*kc+1][2], p31 = sc[2*kc+1][3];
            uint32_t pah0 = pack2(p00, p01);
            uint32_t pah1 = pack2(p10, p11);
            uint32_t pah2 = pack2(p20, p21);
            uint32_t pah3 = pack2(p30, p31);
            __nv_bfloat162 hh;
            *(uint32_t*)&hh = pah0;
            uint32_t pal0 = pack2(p00 - __bfloat162float(hh.x), p01 - __bfloat162float(hh.y));
            *(uint32_t*)&hh = pah1;
            uint32_t pal1 = pack2(p10 - __bfloat162float(hh.x), p11 - __bfloat162float(hh.y));
            *(uint32_t*)&hh = pah2;
            uint32_t pal2 = pack2(p20 - __bfloat162float(hh.x), p21 - __bfloat162float(hh.y));
            *(uint32_t*)&hh = pah3;
            uint32_t pal3 = pack2(p30 - __bfloat162float(hh.x), p31 - __bfloat162float(hh.y));

            const uint32_t kOff = (uint32_t)(kc * 32);
#pragma unroll
            for (int p = 0; p < 4; p++) {
                uint32_t va = kvb + 2 * FA_TILEB
                            + (uint32_t)((p * 16 + bRow) * FA_STRB) + kOff + bCol;
                uint32_t vh0, vh1, vh2, vh3, vl0, vl1, vl2, vl3;
                ldsm4(vh0, vh1, vh2, vh3, va);
                ldsm4(vl0, vl1, vl2, vl3, va + FA_TILEB);
                mma_bf16(oc[2*p],   pah0, pah1, pah2, pah3, vh0, vh1);
                mma_bf16(oc[2*p],   pah0, pah1, pah2, pah3, vl0, vl1);
                mma_bf16(oc[2*p],   pal0, pal1, pal2, pal3, vh0, vh1);
                mma_bf16(oc[2*p+1], pah0, pah1, pah2, pah3, vh2, vh3);
                mma_bf16(oc[2*p+1], pah0, pah1, pah2, pah3, vl2, vl3);
                mma_bf16(oc[2*p+1], pal0, pal1, pal2, pal3, vh2, vh3);
            }
        }
        __syncthreads();
    }

    // ---- epilogue ----
    const int b = bh >> 4;
    const int h = bh & 15;
    const float inv0 = 1.f / l0;
    const float inv1 = 1.f / l1;
    const int row0 = b * SEQ + q0 + wq + g;
    const int row1 = row0 + 8;
#pragma unroll
    for (int nf = 0; nf < 8; nf++) {
        const int col = h * HDIM + nf * 8 + t * 2;
        float y00 = oc[nf][0] * inv0, y01 = oc[nf][1] * inv0;
        float y10 = oc[nf][2] * inv1, y11 = oc[nf][3] * inv1;
        float h00 = __bfloat162float(__float2bfloat16(y00));
        float h01 = __bfloat162float(__float2bfloat16(y01));
        float h10 = __bfloat162float(__float2bfloat16(y10));
        float h11 = __bfloat162float(__float2bfloat16(y11));
        *(uint32_t*)(Ahi + (size_t)row0 * CH + col) = pack2(h00, h01);
        *(uint32_t*)(Alo + (size_t)row0 * CH + col) = pack2(y00 - h00, y01 - h01);
        *(uint32_t*)(Ahi + (size_t)row1 * CH + col) = pack2(h10, h11);
        *(uint32_t*)(Alo + (size_t)row1 * CH + col) = pack2(y10 - h10, y11 - h11);
    }
}

// ---------------------------------------------------------------------------
extern "C" void kernel_launch(void* const* d_in, const int* in_sizes, int n_in,
                              void* d_out, int out_size)
{
    const float* x      = (const float*)d_in[0];
    const float* cosT   = (const float*)d_in[1];
    const float* sinT   = (const float*)d_in[2];
    const float* w_attn = (const float*)d_in[3];
    const float* b_attn = (const float*)d_in[4];
    const float* w_proj = (const float*)d_in[5];
    const float* b_proj = (const float*)d_in[6];
    float* out = (float*)d_out;

    float* qkv;
    cudaGetSymbolAddress((void**)&qkv, d_qkv);

    __nv_bfloat16 *xhi, *xlo, *ahi, *alo, *wahi, *walo, *wphi, *wplo;
    __nv_bfloat16 *qh, *ql, *kh, *kl, *vth, *vtl;
    cudaGetSymbolAddress((void**)&xhi,  d_xhi);
    cudaGetSymbolAddress((void**)&xlo,  d_xlo);
    cudaGetSymbolAddress((void**)&ahi,  d_ahi);
    cudaGetSymbolAddress((void**)&alo,  d_alo);
    cudaGetSymbolAddress((void**)&wahi, d_wahiT);
    cudaGetSymbolAddress((void**)&walo, d_waloT);
    cudaGetSymbolAddress((void**)&wphi, d_wphiT);
    cudaGetSymbolAddress((void**)&wplo, d_wploT);
    cudaGetSymbolAddress((void**)&qh,   d_Qhi);
    cudaGetSymbolAddress((void**)&ql,   d_Qlo);
    cudaGetSymbolAddress((void**)&kh,   d_Khi);
    cudaGetSymbolAddress((void**)&kl,   d_Klo);
    cudaGetSymbolAddress((void**)&vth,  d_VThi);
    cudaGetSymbolAddress((void**)&vtl,  d_VTlo);

    cudaFuncSetAttribute(gemm_mma, cudaFuncAttributeMaxDynamicSharedMemorySize,
                         GM_SMEM_BYTES);
    cudaFuncSetAttribute(flash_mma, cudaFuncAttributeMaxDynamicSharedMemorySize,
                         FA_SMEM_BYTES);

    {
        int n = NROW * CH;
        split_bf16<<<(n / 4 + 255) / 256, 256>>>(x, xhi, xlo, n);
        transpose_split<<<dim3(3 * CH / 32, CH / 32), dim3(32, 8)>>>(
            w_attn, wahi, walo, CH, 3 * CH);
        transpose_split<<<dim3(CH / 32, CH / 32), dim3(32, 8)>>>(
            w_proj, wphi, wplo, CH, CH);
    }

    gemm_mma<<<dim3(3 * CH / 128, NROW / 128), 256, GM_SMEM_BYTES>>>(
        xhi, xlo, wahi, walo, b_attn, qkv, NROW, 3 * CH, CH);

    {
        int total = NROW * (CH / 2);
        rope_split<<<(total + 255) / 256, 256>>>(qkv, cosT, sinT);
    }

    vtrans<<<dim3(SEQ / 32, HDIM / 32, BATCH * NHEAD), dim3(32, 8)>>>();

    flash_mma<<<dim3(SEQ / 64, BATCH * NHEAD), 128, FA_SMEM_BYTES>>>(
        qh, ql, kh, kl, vth, vtl, ahi, alo);

    gemm_mma<<<dim3(CH / 128, NROW / 128), 256, GM_SMEM_BYTES>>>(
        ahi, alo, wphi, wplo, b_proj, out, NROW, CH, CH);
}

// round 8
// speedup vs baseline: 2.9588x; 1.0018x over previous
#include <cuda_runtime.h>
#include <cuda_bf16.h>
#include <math.h>
#include <stdint.h>

// ---------------------------------------------------------------------------
// CausalSelfAttention (B=2,T=2048,C=1024,H=16,HD=64)
// R8: R7 + fused RoPE/split into QKV GEMM epilogue (drops d_qkv + rope_split)
//     + ldmatrix.trans for V in flash (drops vtrans + VT buffers).
// ---------------------------------------------------------------------------

#define BATCH 2
#define SEQ   2048
#define CH    1024
#define NHEAD 16
#define HDIM  64
#define NROW  (BATCH * SEQ)

// ---------------- scratch ----------------
__device__ __nv_bfloat16 d_xhi[NROW * CH];
__device__ __nv_bfloat16 d_xlo[NROW * CH];
__device__ __nv_bfloat16 d_ahi[NROW * CH];
__device__ __nv_bfloat16 d_alo[NROW * CH];
__device__ __nv_bfloat16 d_wahiT[3 * CH * CH];
__device__ __nv_bfloat16 d_waloT[3 * CH * CH];
__device__ __nv_bfloat16 d_wphiT[CH * CH];
__device__ __nv_bfloat16 d_wploT[CH * CH];

__device__ __nv_bfloat16 d_Qhi[NROW * CH];
__device__ __nv_bfloat16 d_Qlo[NROW * CH];
__device__ __nv_bfloat16 d_Khi[NROW * CH];
__device__ __nv_bfloat16 d_Klo[NROW * CH];
__device__ __nv_bfloat16 d_Vhi[NROW * CH];
__device__ __nv_bfloat16 d_Vlo[NROW * CH];

// ---------------- helpers ----------------
__device__ __forceinline__ uint32_t smem_u32(const void* p) {
    uint32_t a;
    asm("{ .reg .u64 t; cvta.to.shared.u64 t, %1; cvt.u32.u64 %0, t; }"
        : "=r"(a) : "l"(p));
    return a;
}

#define CP_ASYNC16(dst_u32, src_ptr) \
    asm volatile("cp.async.cg.shared.global [%0], [%1], 16;" \
                 :: "r"(dst_u32), "l"(src_ptr) : "memory")
#define CP_COMMIT() asm volatile("cp.async.commit_group;" ::: "memory")
#define CP_WAIT(n)  asm volatile("cp.async.wait_group %0;" :: "n"(n) : "memory")

__device__ __forceinline__ void mma_bf16(float c[4], uint32_t a0, uint32_t a1,
                                         uint32_t a2, uint32_t a3,
                                         uint32_t b0, uint32_t b1) {
    asm volatile(
        "mma.sync.aligned.m16n8k16.row.col.f32.bf16.bf16.f32 "
        "{%0,%1,%2,%3}, {%4,%5,%6,%7}, {%8,%9}, {%0,%1,%2,%3};"
        : "+f"(c[0]), "+f"(c[1]), "+f"(c[2]), "+f"(c[3])
        : "r"(a0), "r"(a1), "r"(a2), "r"(a3), "r"(b0), "r"(b1));
}

__device__ __forceinline__ void ldsm4(uint32_t& r0, uint32_t& r1,
                                      uint32_t& r2, uint32_t& r3, uint32_t a) {
    asm volatile("ldmatrix.sync.aligned.m8n8.x4.shared.b16 {%0,%1,%2,%3}, [%4];"
                 : "=r"(r0), "=r"(r1), "=r"(r2), "=r"(r3) : "r"(a));
}

__device__ __forceinline__ void ldsm4t(uint32_t& r0, uint32_t& r1,
                                       uint32_t& r2, uint32_t& r3, uint32_t a) {
    asm volatile("ldmatrix.sync.aligned.m8n8.x4.trans.shared.b16 {%0,%1,%2,%3}, [%4];"
                 : "=r"(r0), "=r"(r1), "=r"(r2), "=r"(r3) : "r"(a));
}

__device__ __forceinline__ uint32_t pack2(float a, float b) {
    __nv_bfloat162 h = __floats2bfloat162_rn(a, b);
    return *(uint32_t*)&h;
}

// ---------------------------------------------------------------------------
// common GEMM tile config
// ---------------------------------------------------------------------------
#define GM_BK 32
#define GM_AS 40
#define GM_ROWB (GM_AS * 2)
#define GM_BUFB (128 * GM_ROWB)
#define GM_STAGEB (4 * GM_BUFB)
#define GM_SMEM_BYTES (2 * GM_STAGEB)

// mainloop shared by both GEMMs (macro-free: function with accumulators by ref)
struct GemmCore {
    uint32_t smb;
    int tid, wid, lid, wm, wn, m0, n0, K;
    const __nv_bfloat16 *Ahi, *Alo, *Bhi, *Blo;

    __device__ __forceinline__ void run(float c[4][4][4]) {
        const int aRow = lid & 15;
        const int aCol = (lid >> 4) << 4;
        const int bRow = (lid & 7) + ((lid & 16) >> 1);
        const int bCol = ((lid >> 3) & 1) << 4;
        const int KT = K / GM_BK;

        auto issue_stage = [&](int st, int kt) {
            const uint32_t base = smb + (uint32_t)st * GM_STAGEB;
#pragma unroll
            for (int i = 0; i < 8; i++) {
                int id  = tid + i * 256;
                int buf = id >> 9;
                int cc  = id & 511;
                int r   = cc >> 2;
                int kc  = (cc & 3) * 8;
                uint32_t dst = base + (uint32_t)buf * GM_BUFB
                             + (uint32_t)(r * GM_ROWB + kc * 2);
                const __nv_bfloat16* src;
                if (buf == 0)      src = Ahi + (size_t)(m0 + r) * K + kt + kc;
                else if (buf == 1) src = Alo + (size_t)(m0 + r) * K + kt + kc;
                else if (buf == 2) src = Bhi + (size_t)(n0 + r) * K + kt + kc;
                else               src = Blo + (size_t)(n0 + r) * K + kt + kc;
                CP_ASYNC16(dst, src);
            }
            CP_COMMIT();
        };

        issue_stage(0, 0);

        for (int it = 0; it < KT; it++) {
            if (it + 1 < KT) {
                issue_stage((it + 1) & 1, (it + 1) * GM_BK);
                CP_WAIT(1);
            } else {
                CP_WAIT(0);
            }
            __syncthreads();

            const uint32_t stb = smb + (uint32_t)(it & 1) * GM_STAGEB;

#pragma unroll
            for (int ks = 0; ks < GM_BK / 16; ks++) {
                const uint32_t kOff = (uint32_t)(ks * 32);
                uint32_t ah[4][4], al[4][4];
#pragma unroll
                for (int mt = 0; mt < 4; mt++) {
                    uint32_t ra = stb + (uint32_t)((wm + mt * 16 + aRow) * GM_ROWB)
                                + kOff + aCol;
                    ldsm4(ah[mt][0], ah[mt][1], ah[mt][2], ah[mt][3], ra);
                    ldsm4(al[mt][0], al[mt][1], al[mt][2], al[mt][3], ra + GM_BUFB);
                }
                uint32_t bh[4][2], bl[4][2];
#pragma unroll
                for (int p = 0; p < 2; p++) {
                    uint32_t rb = stb + 2 * GM_BUFB
                                + (uint32_t)((wn + p * 16 + bRow) * GM_ROWB)
                                + kOff + bCol;
                    ldsm4(bh[2*p][0], bh[2*p][1], bh[2*p+1][0], bh[2*p+1][1], rb);
                    ldsm4(bl[2*p][0], bl[2*p][1], bl[2*p+1][0], bl[2*p+1][1],
                          rb + GM_BUFB);
                }
#pragma unroll
                for (int nt = 0; nt < 4; nt++)
#pragma unroll
                    for (int mt = 0; mt < 4; mt++) {
                        mma_bf16(c[mt][nt], ah[mt][0], ah[mt][1], ah[mt][2], ah[mt][3],
                                 bh[nt][0], bh[nt][1]);
                        mma_bf16(c[mt][nt], ah[mt][0], ah[mt][1], ah[mt][2], ah[mt][3],
                                 bl[nt][0], bl[nt][1]);
                        mma_bf16(c[mt][nt], al[mt][0], al[mt][1], al[mt][2], al[mt][3],
                                 bh[nt][0], bh[nt][1]);
                    }
            }
            __syncthreads();
        }
    }
};

// ---------------------------------------------------------------------------
// QKV GEMM with fused bias + RoPE + head split + hi/lo split epilogue
// ---------------------------------------------------------------------------
__global__ __launch_bounds__(256, 2)
void gemm_qkv(const __nv_bfloat16* __restrict__ Ahi,
              const __nv_bfloat16* __restrict__ Alo,
              const __nv_bfloat16* __restrict__ Bhi,
              const __nv_bfloat16* __restrict__ Blo,
              const float* __restrict__ bias,
              const float* __restrict__ cosT,
              const float* __restrict__ sinT)
{
    extern __shared__ char sm[];
    GemmCore gc;
    gc.smb = smem_u32(sm);
    gc.tid = threadIdx.x;
    gc.wid = gc.tid >> 5;
    gc.lid = gc.tid & 31;
    gc.wm  = (gc.wid >> 2) * 64;
    gc.wn  = (gc.wid & 3) * 32;
    gc.m0  = blockIdx.y * 128;
    gc.n0  = blockIdx.x * 128;
    gc.K   = CH;
    gc.Ahi = Ahi; gc.Alo = Alo; gc.Bhi = Bhi; gc.Blo = Blo;

    float c[4][4][4];
#pragma unroll
    for (int i = 0; i < 4; i++)
#pragma unroll
        for (int j = 0; j < 4; j++)
#pragma unroll
            for (int q = 0; q < 4; q++) c[i][j][q] = 0.f;

    gc.run(c);

    const int gid = gc.lid >> 2;
    const int tig = gc.lid & 3;

#pragma unroll
    for (int mt = 0; mt < 4; mt++) {
#pragma unroll
        for (int nt = 0; nt < 4; nt++) {
            const int col = gc.n0 + gc.wn + nt * 8 + tig * 2;
            float2 b01 = *(const float2*)(bias + col);
            const int seg = col >> 10;           // 0=q 1=k 2=v
            const int cc  = col & 1023;
            const int h   = cc >> 6;
            const int d   = cc & 63;
            const int pr  = d >> 1;
            __nv_bfloat16* Hi = (seg == 0) ? d_Qhi : (seg == 1) ? d_Khi : d_Vhi;
            __nv_bfloat16* Lo = (seg == 0) ? d_Qlo : (seg == 1) ? d_Klo : d_Vlo;
#pragma unroll
            for (int half = 0; half < 2; half++) {
                const int row = gc.m0 + gc.wm + mt * 16 + gid + half * 8;
                const int t   = row & (SEQ - 1);
                const int b   = row >> 11;
                float e = c[mt][nt][half * 2 + 0] + b01.x;
                float o = c[mt][nt][half * 2 + 1] + b01.y;
                if (seg < 2) {
                    float cs = cosT[t * 32 + pr];
                    float sn = sinT[t * 32 + pr];
                    float re = e * cs - o * sn;
                    float ro = e * sn + o * cs;
                    e = re; o = ro;
                }
                float eh = __bfloat162float(__float2bfloat16(e));
                float oh = __bfloat162float(__float2bfloat16(o));
                size_t off = ((size_t)(b * NHEAD + h) * SEQ + t) * HDIM + d;
                *(uint32_t*)(Hi + off) = pack2(eh, oh);
                *(uint32_t*)(Lo + off) = pack2(e - eh, o - oh);
            }
        }
    }
}

// ---------------------------------------------------------------------------
// generic GEMM (projection): fp32 output + bias
// ---------------------------------------------------------------------------
__global__ __launch_bounds__(256, 2)
void gemm_mma(const __nv_bfloat16* __restrict__ Ahi,
              const __nv_bfloat16* __restrict__ Alo,
              const __nv_bfloat16* __restrict__ Bhi,
              const __nv_bfloat16* __restrict__ Blo,
              const float* __restrict__ bias, float* __restrict__ C,
              int M, int N, int K)
{
    extern __shared__ char sm[];
    GemmCore gc;
    gc.smb = smem_u32(sm);
    gc.tid = threadIdx.x;
    gc.wid = gc.tid >> 5;
    gc.lid = gc.tid & 31;
    gc.wm  = (gc.wid >> 2) * 64;
    gc.wn  = (gc.wid & 3) * 32;
    gc.m0  = blockIdx.y * 128;
    gc.n0  = blockIdx.x * 128;
    gc.K   = K;
    gc.Ahi = Ahi; gc.Alo = Alo; gc.Bhi = Bhi; gc.Blo = Blo;

    float c[4][4][4];
#pragma unroll
    for (int i = 0; i < 4; i++)
#pragma unroll
        for (int j = 0; j < 4; j++)
#pragma unroll
            for (int q = 0; q < 4; q++) c[i][j][q] = 0.f;

    gc.run(c);

    const int gid = gc.lid >> 2;
    const int tig = gc.lid & 3;
#pragma unroll
    for (int mt = 0; mt < 4; mt++) {
#pragma unroll
        for (int nt = 0; nt < 4; nt++) {
            const int row = gc.m0 + gc.wm + mt * 16 + gid;
            const int col = gc.n0 + gc.wn + nt * 8 + tig * 2;
            float2 b01 = *(const float2*)(bias + col);
            float2 v0 = make_float2(c[mt][nt][0] + b01.x, c[mt][nt][1] + b01.y);
            float2 v1 = make_float2(c[mt][nt][2] + b01.x, c[mt][nt][3] + b01.y);
            *(float2*)(C + (size_t)row * N + col)       = v0;
            *(float2*)(C + (size_t)(row + 8) * N + col) = v1;
        }
    }
}

// ---------------------------------------------------------------------------
// fp32 -> bf16 hi/lo split (x)
// ---------------------------------------------------------------------------
__global__ void split_bf16(const float* __restrict__ X,
                           __nv_bfloat16* __restrict__ hi,
                           __nv_bfloat16* __restrict__ lo, int n)
{
    int i = (blockIdx.x * blockDim.x + threadIdx.x) * 4;
    if (i >= n) return;
    float4 v = *(const float4*)(X + i);
    __nv_bfloat16 h0 = __float2bfloat16(v.x);
    __nv_bfloat16 h1 = __float2bfloat16(v.y);
    __nv_bfloat16 h2 = __float2bfloat16(v.z);
    __nv_bfloat16 h3 = __float2bfloat16(v.w);
    __nv_bfloat162 H01; H01.x = h0; H01.y = h1;
    __nv_bfloat162 H23; H23.x = h2; H23.y = h3;
    *(__nv_bfloat162*)(hi + i)     = H01;
    *(__nv_bfloat162*)(hi + i + 2) = H23;
    __nv_bfloat162 L01, L23;
    L01.x = __float2bfloat16(v.x - __bfloat162float(h0));
    L01.y = __float2bfloat16(v.y - __bfloat162float(h1));
    L23.x = __float2bfloat16(v.z - __bfloat162float(h2));
    L23.y = __float2bfloat16(v.w - __bfloat162float(h3));
    *(__nv_bfloat162*)(lo + i)     = L01;
    *(__nv_bfloat162*)(lo + i + 2) = L23;
}

// ---------------------------------------------------------------------------
// transpose + split: W[K,N] fp32 -> Thi/Tlo[N,K] bf16
// ---------------------------------------------------------------------------
__global__ void transpose_split(const float* __restrict__ W,
                                __nv_bfloat16* __restrict__ Thi,
                                __nv_bfloat16* __restrict__ Tlo,
                                int K, int N)
{
    __shared__ float tile[32][33];
    const int n0 = blockIdx.x * 32;
    const int k0 = blockIdx.y * 32;
    const int tx = threadIdx.x;
    const int ty = threadIdx.y;
#pragma unroll
    for (int i = 0; i < 32; i += 8)
        tile[ty + i][tx] = W[(size_t)(k0 + ty + i) * N + n0 + tx];
    __syncthreads();
#pragma unroll
    for (int i = 0; i < 32; i += 8) {
        float v = tile[tx][ty + i];
        __nv_bfloat16 h = __float2bfloat16(v);
        size_t o = (size_t)(n0 + ty + i) * K + k0 + tx;
        Thi[o] = h;
        Tlo[o] = __float2bfloat16(v - __bfloat162float(h));
    }
}

// ---------------------------------------------------------------------------
// Flash attention (mma.sync bf16 hi/lo; ldmatrix + ldmatrix.trans for V)
// ---------------------------------------------------------------------------
#define FA_STRB 144
#define FA_TILEB (64 * FA_STRB)
#define FA_QBYTES (2 * FA_TILEB)
#define FA_KVSTAGE (4 * FA_TILEB)
#define FA_SMEM_BYTES (FA_QBYTES + 2 * FA_KVSTAGE)

__global__ __launch_bounds__(128)
void flash_mma(const __nv_bfloat16* __restrict__ Qhi,
               const __nv_bfloat16* __restrict__ Qlo,
               const __nv_bfloat16* __restrict__ Khi,
               const __nv_bfloat16* __restrict__ Klo,
               const __nv_bfloat16* __restrict__ Vhi,
               const __nv_bfloat16* __restrict__ Vlo,
               __nv_bfloat16* __restrict__ Ahi,
               __nv_bfloat16* __restrict__ Alo)
{
    extern __shared__ char smem[];
    const uint32_t smb = smem_u32(smem);
    const int tid = threadIdx.x;
    const int wid = tid >> 5;
    const int lid = tid & 31;
    const int g   = lid >> 2;
    const int t   = lid & 3;
    const int wq  = wid * 16;
    const int qt  = gridDim.x - 1 - blockIdx.x;
    const int bh  = blockIdx.y;
    const int q0  = qt * 64;

    const int aRow = lid & 15;
    const int aCol = (lid >> 4) << 4;
    const int bRow = (lid & 7) + ((lid & 16) >> 1);
    const int bCol = ((lid >> 3) & 1) << 4;
    // trans-load lane mapping for V [k][d]: row = (lid&7) + k-half, col-half by lid>>4
    const int vRow = (lid & 7) + ((lid >> 3) & 1) * 8;
    const int vColH = (lid >> 4) * 8;

    const size_t base = (size_t)bh * SEQ * HDIM;
    const __nv_bfloat16* Qhib = Qhi + base;
    const __nv_bfloat16* Qlob = Qlo + base;
    const __nv_bfloat16* Khib = Khi + base;
    const __nv_bfloat16* Klob = Klo + base;
    const __nv_bfloat16* Vhib = Vhi + base;
    const __nv_bfloat16* Vlob = Vlo + base;

    auto issue_kv = [&](int st, int kt) {
#pragma unroll
        for (int i = 0; i < 16; i++) {
            int id  = tid + i * 128;
            int buf = id >> 9;
            int cc  = id & 511;
            int r   = cc >> 3;
            int c8  = (cc & 7) * 8;
            uint32_t dst = smb + FA_QBYTES + (uint32_t)st * FA_KVSTAGE
                         + (uint32_t)buf * FA_TILEB + (uint32_t)(r * FA_STRB + c8 * 2);
            const __nv_bfloat16* src;
            if (buf == 0)      src = Khib + (size_t)(kt + r) * HDIM + c8;
            else if (buf == 1) src = Klob + (size_t)(kt + r) * HDIM + c8;
            else if (buf == 2) src = Vhib + (size_t)(kt + r) * HDIM + c8;
            else               src = Vlob + (size_t)(kt + r) * HDIM + c8;
            CP_ASYNC16(dst, src);
        }
        CP_COMMIT();
    };

    issue_kv(0, 0);

#pragma unroll
    for (int i = 0; i < 4; i++) {
        int id = tid + i * 128;
        int r  = id >> 3;
        int c8 = (id & 7) * 8;
        uint4 vh = *(const uint4*)(Qhib + (size_t)(q0 + r) * HDIM + c8);
        uint4 vl = *(const uint4*)(Qlob + (size_t)(q0 + r) * HDIM + c8);
        *(uint4*)(smem + r * FA_STRB + c8 * 2) = vh;
        *(uint4*)(smem + FA_TILEB + r * FA_STRB + c8 * 2) = vl;
    }

    float m0 = -INFINITY, m1 = -INFINITY, l0 = 0.f, l1 = 0.f;
    float oc[8][4];
#pragma unroll
    for (int nf = 0; nf < 8; nf++)
#pragma unroll
        for (int cidx = 0; cidx < 4; cidx++) oc[nf][cidx] = 0.f;

    for (int jt = 0; jt <= qt; jt++) {
        if (jt < qt) {
            issue_kv((jt + 1) & 1, (jt + 1) * 64);
            CP_WAIT(1);
        } else {
            CP_WAIT(0);
        }
        __syncthreads();

        const uint32_t kvb = smb + FA_QBYTES + (uint32_t)(jt & 1) * FA_KVSTAGE;

        // ---- S = Q @ K^T (3-term) ----
        float sc[8][4];
#pragma unroll
        for (int nf = 0; nf < 8; nf++)
#pragma unroll
            for (int cidx = 0; cidx < 4; cidx++) sc[nf][cidx] = 0.f;

#pragma unroll
        for (int kc = 0; kc < 4; kc++) {
            const uint32_t kOff = (uint32_t)(kc * 32);
            uint32_t qh[4], ql[4];
            uint32_t qa = smb + (uint32_t)((wq + aRow) * FA_STRB) + kOff + aCol;
            ldsm4(qh[0], qh[1], qh[2], qh[3], qa);
            ldsm4(ql[0], ql[1], ql[2], ql[3], qa + FA_TILEB);
#pragma unroll
            for (int p = 0; p < 4; p++) {
                uint32_t ka = kvb + (uint32_t)((p * 16 + bRow) * FA_STRB)
                            + kOff + bCol;
                uint32_t kh0, kh1, kh2, kh3, kl0, kl1, kl2, kl3;
                ldsm4(kh0, kh1, kh2, kh3, ka);
                ldsm4(kl0, kl1, kl2, kl3, ka + FA_TILEB);
                mma_bf16(sc[2*p],   qh[0], qh[1], qh[2], qh[3], kh0, kh1);
                mma_bf16(sc[2*p],   qh[0], qh[1], qh[2], qh[3], kl0, kl1);
                mma_bf16(sc[2*p],   ql[0], ql[1], ql[2], ql[3], kh0, kh1);
                mma_bf16(sc[2*p+1], qh[0], qh[1], qh[2], qh[3], kh2, kh3);
                mma_bf16(sc[2*p+1], qh[0], qh[1], qh[2], qh[3], kl2, kl3);
                mma_bf16(sc[2*p+1], ql[0], ql[1], ql[2], ql[3], kh2, kh3);
            }
        }

#pragma unroll
        for (int nf = 0; nf < 8; nf++)
#pragma unroll
            for (int cidx = 0; cidx < 4; cidx++) sc[nf][cidx] *= 0.125f;

        if (jt == qt) {
            const int qg0 = q0 + wq + g;
            const int qg1 = qg0 + 8;
#pragma unroll
            for (int nf = 0; nf < 8; nf++) {
                const int kb = q0 + nf * 8 + t * 2;
                if (kb     > qg0) sc[nf][0] = -INFINITY;
                if (kb + 1 > qg0) sc[nf][1] = -INFINITY;
                if (kb     > qg1) sc[nf][2] = -INFINITY;
                if (kb + 1 > qg1) sc[nf][3] = -INFINITY;
            }
        }

        // ---- online softmax ----
        float a0 = -INFINITY, a1 = -INFINITY;
#pragma unroll
        for (int nf = 0; nf < 8; nf++) {
            a0 = fmaxf(a0, fmaxf(sc[nf][0], sc[nf][1]));
            a1 = fmaxf(a1, fmaxf(sc[nf][2], sc[nf][3]));
        }
        a0 = fmaxf(a0, __shfl_xor_sync(0xffffffffu, a0, 1));
        a0 = fmaxf(a0, __shfl_xor_sync(0xffffffffu, a0, 2));
        a1 = fmaxf(a1, __shfl_xor_sync(0xffffffffu, a1, 1));
        a1 = fmaxf(a1, __shfl_xor_sync(0xffffffffu, a1, 2));

        float mn0 = fmaxf(m0, a0), mn1 = fmaxf(m1, a1);
        float cr0 = __expf(m0 - mn0), cr1 = __expf(m1 - mn1);
        float rs0 = 0.f, rs1 = 0.f;
#pragma unroll
        for (int nf = 0; nf < 8; nf++) {
            sc[nf][0] = __expf(sc[nf][0] - mn0);
            sc[nf][1] = __expf(sc[nf][1] - mn0);
            sc[nf][2] = __expf(sc[nf][2] - mn1);
            sc[nf][3] = __expf(sc[nf][3] - mn1);
            rs0 += sc[nf][0] + sc[nf][1];
            rs1 += sc[nf][2] + sc[nf][3];
        }
        rs0 += __shfl_xor_sync(0xffffffffu, rs0, 1);
        rs0 += __shfl_xor_sync(0xffffffffu, rs0, 2);
        rs1 += __shfl_xor_sync(0xffffffffu, rs1, 1);
        rs1 += __shfl_xor_sync(0xffffffffu, rs1, 2);
        l0 = l0 * cr0 + rs0;  m0 = mn0;
        l1 = l1 * cr1 + rs1;  m1 = mn1;
#pragma unroll
        for (int nf = 0; nf < 8; nf++) {
            oc[nf][0] *= cr0; oc[nf][1] *= cr0;
            oc[nf][2] *= cr1; oc[nf][3] *= cr1;
        }

        // ---- O += P @ V (3-term, V via ldmatrix.trans from [k][d]) ----
#pragma unroll
        for (int kc = 0; kc < 4; kc++) {
            float p00 = sc[2*kc][0],   p01 = sc[2*kc][1];
            float p10 = sc[2*kc][2],   p11 = sc[2*kc][3];
            float p20 = sc[2*kc+1][0], p21 = sc[2*kc+1][1];
            float p30 = sc[2*kc+1][2], p31 = sc[2*kc+1][3];
            uint32_t pah0 = pack2(p00, p01);
            uint32_t pah1 = pack2(p10, p11);
            uint32_t pah2 = pack2(p20, p21);
            uint32_t pah3 = pack2(p30, p31);
            __nv_bfloat162 hh;
            *(uint32_t*)&hh = pah0;
            uint32_t pal0 = pack2(p00 - __bfloat162float(hh.x), p01 - __bfloat162float(hh.y));
            *(uint32_t*)&hh = pah1;
            uint32_t pal1 = pack2(p10 - __bfloat162float(hh.x), p11 - __bfloat162float(hh.y));
            *(uint32_t*)&hh = pah2;
            uint32_t pal2 = pack2(p20 - __bfloat162float(hh.x), p21 - __bfloat162float(hh.y));
            *(uint32_t*)&hh = pah3;
            uint32_t pal3 = pack2(p30 - __bfloat162float(hh.x), p31 - __bfloat162float(hh.y));

            // V rows = keys kc*16 + vRow; cols = d block
#pragma unroll
            for (int p = 0; p < 4; p++) {
                uint32_t va = kvb + 2 * FA_TILEB
                            + (uint32_t)((kc * 16 + vRow) * FA_STRB)
                            + (uint32_t)((p * 16 + vColH) * 2);
                uint32_t vh0, vh1, vh2, vh3, vl0, vl1, vl2, vl3;
                ldsm4t(vh0, vh1, vh2, vh3, va);
                ldsm4t(vl0, vl1, vl2, vl3, va + FA_TILEB);
                mma_bf16(oc[2*p],   pah0, pah1, pah2, pah3, vh0, vh1);
                mma_bf16(oc[2*p],   pah0, pah1, pah2, pah3, vl0, vl1);
                mma_bf16(oc[2*p],   pal0, pal1, pal2, pal3, vh0, vh1);
                mma_bf16(oc[2*p+1], pah0, pah1, pah2, pah3, vh2, vh3);
                mma_bf16(oc[2*p+1], pah0, pah1, pah2, pah3, vl2, vl3);
                mma_bf16(oc[2*p+1], pal0, pal1, pal2, pal3, vh2, vh3);
            }
        }
        __syncthreads();
    }

    // ---- epilogue ----
    const int b = bh >> 4;
    const int h = bh & 15;
    const float inv0 = 1.f / l0;
    const float inv1 = 1.f / l1;
    const int row0 = b * SEQ + q0 + wq + g;
    const int row1 = row0 + 8;
#pragma unroll
    for (int nf = 0; nf < 8; nf++) {
        const int col = h * HDIM + nf * 8 + t * 2;
        float y00 = oc[nf][0] * inv0, y01 = oc[nf][1] * inv0;
        float y10 = oc[nf][2] * inv1, y11 = oc[nf][3] * inv1;
        float h00 = __bfloat162float(__float2bfloat16(y00));
        float h01 = __bfloat162float(__float2bfloat16(y01));
        float h10 = __bfloat162float(__float2bfloat16(y10));
        float h11 = __bfloat162float(__float2bfloat16(y11));
        *(uint32_t*)(Ahi + (size_t)row0 * CH + col) = pack2(h00, h01);
        *(uint32_t*)(Alo + (size_t)row0 * CH + col) = pack2(y00 - h00, y01 - h01);
        *(uint32_t*)(Ahi + (size_t)row1 * CH + col) = pack2(h10, h11);
        *(uint32_t*)(Alo + (size_t)row1 * CH + col) = pack2(y10 - h10, y11 - h11);
    }
}

// ---------------------------------------------------------------------------
extern "C" void kernel_launch(void* const* d_in, const int* in_sizes, int n_in,
                              void* d_out, int out_size)
{
    const float* x      = (const float*)d_in[0];
    const float* cosT   = (const float*)d_in[1];
    const float* sinT   = (const float*)d_in[2];
    const float* w_attn = (const float*)d_in[3];
    const float* b_attn = (const float*)d_in[4];
    const float* w_proj = (const float*)d_in[5];
    const float* b_proj = (const float*)d_in[6];
    float* out = (float*)d_out;

    __nv_bfloat16 *xhi, *xlo, *ahi, *alo, *wahi, *walo, *wphi, *wplo;
    __nv_bfloat16 *qh, *ql, *kh, *kl, *vh, *vl;
    cudaGetSymbolAddress((void**)&xhi,  d_xhi);
    cudaGetSymbolAddress((void**)&xlo,  d_xlo);
    cudaGetSymbolAddress((void**)&ahi,  d_ahi);
    cudaGetSymbolAddress((void**)&alo,  d_alo);
    cudaGetSymbolAddress((void**)&wahi, d_wahiT);
    cudaGetSymbolAddress((void**)&walo, d_waloT);
    cudaGetSymbolAddress((void**)&wphi, d_wphiT);
    cudaGetSymbolAddress((void**)&wplo, d_wploT);
    cudaGetSymbolAddress((void**)&qh,   d_Qhi);
    cudaGetSymbolAddress((void**)&ql,   d_Qlo);
    cudaGetSymbolAddress((void**)&kh,   d_Khi);
    cudaGetSymbolAddress((void**)&kl,   d_Klo);
    cudaGetSymbolAddress((void**)&vh,   d_Vhi);
    cudaGetSymbolAddress((void**)&vl,   d_Vlo);

    cudaFuncSetAttribute(gemm_qkv, cudaFuncAttributeMaxDynamicSharedMemorySize,
                         GM_SMEM_BYTES);
    cudaFuncSetAttribute(gemm_mma, cudaFuncAttributeMaxDynamicSharedMemorySize,
                         GM_SMEM_BYTES);
    cudaFuncSetAttribute(flash_mma, cudaFuncAttributeMaxDynamicSharedMemorySize,
                         FA_SMEM_BYTES);

    {
        int n = NROW * CH;
        split_bf16<<<(n / 4 + 255) / 256, 256>>>(x, xhi, xlo, n);
        transpose_split<<<dim3(3 * CH / 32, CH / 32), dim3(32, 8)>>>(
            w_attn, wahi, walo, CH, 3 * CH);
        transpose_split<<<dim3(CH / 32, CH / 32), dim3(32, 8)>>>(
            w_proj, wphi, wplo, CH, CH);
    }

    // 1) QKV GEMM with fused RoPE/split epilogue
    gemm_qkv<<<dim3(3 * CH / 128, NROW / 128), 256, GM_SMEM_BYTES>>>(
        xhi, xlo, wahi, walo, b_attn, cosT, sinT);

    // 2) flash attention -> proj operands
    flash_mma<<<dim3(SEQ / 64, BATCH * NHEAD), 128, FA_SMEM_BYTES>>>(
        qh, ql, kh, kl, vh, vl, ahi, alo);

    // 3) projection GEMM
    gemm_mma<<<dim3(CH / 128, NROW / 128), 256, GM_SMEM_BYTES>>>(
        ahi, alo, wphi, wplo, b_proj, out, NROW, CH, CH);
}

// round 9
// speedup vs baseline: 6.6590x; 2.2506x over previous
#include <cuda_runtime.h>
#include <cuda_fp16.h>
#include <math.h>
#include <stdint.h>

// ---------------------------------------------------------------------------
// CausalSelfAttention (B=2,T=2048,C=1024,H=16,HD=64)
// R9: fp16 single-pass mma.sync everywhere (3x fewer MMAs than bf16 hi/lo),
//     3-stage cp.async pipeline in dense GEMMs.
// ---------------------------------------------------------------------------

#define BATCH 2
#define SEQ   2048
#define CH    1024
#define NHEAD 16
#define HDIM  64
#define NROW  (BATCH * SEQ)

// ---------------- scratch ----------------
__device__ __half d_x16[NROW * CH];
__device__ __half d_a16[NROW * CH];
__device__ __half d_wa16T[3 * CH * CH];   // [N][K]
__device__ __half d_wp16T[CH * CH];
__device__ __half d_Q16[NROW * CH];
__device__ __half d_K16[NROW * CH];
__device__ __half d_V16[NROW * CH];

// ---------------- helpers ----------------
__device__ __forceinline__ uint32_t smem_u32(const void* p) {
    uint32_t a;
    asm("{ .reg .u64 t; cvta.to.shared.u64 t, %1; cvt.u32.u64 %0, t; }"
        : "=r"(a) : "l"(p));
    return a;
}

#define CP_ASYNC16(dst_u32, src_ptr) \
    asm volatile("cp.async.cg.shared.global [%0], [%1], 16;" \
                 :: "r"(dst_u32), "l"(src_ptr) : "memory")
#define CP_COMMIT() asm volatile("cp.async.commit_group;" ::: "memory")
#define CP_WAIT(n)  asm volatile("cp.async.wait_group %0;" :: "n"(n) : "memory")

__device__ __forceinline__ void mma_f16(float c[4], uint32_t a0, uint32_t a1,
                                        uint32_t a2, uint32_t a3,
                                        uint32_t b0, uint32_t b1) {
    asm volatile(
        "mma.sync.aligned.m16n8k16.row.col.f32.f16.f16.f32 "
        "{%0,%1,%2,%3}, {%4,%5,%6,%7}, {%8,%9}, {%0,%1,%2,%3};"
        : "+f"(c[0]), "+f"(c[1]), "+f"(c[2]), "+f"(c[3])
        : "r"(a0), "r"(a1), "r"(a2), "r"(a3), "r"(b0), "r"(b1));
}

__device__ __forceinline__ void ldsm4(uint32_t& r0, uint32_t& r1,
                                      uint32_t& r2, uint32_t& r3, uint32_t a) {
    asm volatile("ldmatrix.sync.aligned.m8n8.x4.shared.b16 {%0,%1,%2,%3}, [%4];"
                 : "=r"(r0), "=r"(r1), "=r"(r2), "=r"(r3) : "r"(a));
}

__device__ __forceinline__ void ldsm4t(uint32_t& r0, uint32_t& r1,
                                       uint32_t& r2, uint32_t& r3, uint32_t a) {
    asm volatile("ldmatrix.sync.aligned.m8n8.x4.trans.shared.b16 {%0,%1,%2,%3}, [%4];"
                 : "=r"(r0), "=r"(r1), "=r"(r2), "=r"(r3) : "r"(a));
}

__device__ __forceinline__ uint32_t pack2h(float a, float b) {
    __half2 h = __floats2half2_rn(a, b);
    return *(uint32_t*)&h;
}

// ---------------------------------------------------------------------------
// GEMM tile config: 128x128, BK=32, 3-stage cp.async pipeline
// ---------------------------------------------------------------------------
#define GM_BK 32
#define GM_ROWB 80                         // 32 fp16 + 8 pad = 80 bytes
#define GM_BUFB (128 * GM_ROWB)            // 10240 B per matrix buffer
#define GM_STAGEB (2 * GM_BUFB)            // A + B
#define GM_NSTAGE 3
#define GM_SMEM_BYTES (GM_NSTAGE * GM_STAGEB)

struct GemmCore {
    uint32_t smb;
    int tid, wid, lid, wm, wn, m0, n0, K;
    const __half *A, *B;

    __device__ __forceinline__ void issue_stage(int st, int kt) {
        const uint32_t base = smb + (uint32_t)st * GM_STAGEB;
#pragma unroll
        for (int i = 0; i < 4; i++) {
            int id  = tid + i * 256;           // 0..1023
            int buf = id >> 9;                 // 0..1
            int cc  = id & 511;
            int r   = cc >> 2;                 // 0..127
            int kc  = (cc & 3) * 8;
            uint32_t dst = base + (uint32_t)buf * GM_BUFB
                         + (uint32_t)(r * GM_ROWB + kc * 2);
            const __half* src = (buf == 0)
                ? A + (size_t)(m0 + r) * K + kt + kc
                : B + (size_t)(n0 + r) * K + kt + kc;
            CP_ASYNC16(dst, src);
        }
        CP_COMMIT();
    }

    __device__ __forceinline__ void run(float c[4][4][4]) {
        const int aRow = lid & 15;
        const int aCol = (lid >> 4) << 4;
        const int bRow = (lid & 7) + ((lid & 16) >> 1);
        const int bCol = ((lid >> 3) & 1) << 4;
        const int KT = K / GM_BK;

        issue_stage(0, 0);
        issue_stage(1, GM_BK);

        for (int it = 0; it < KT; it++) {
            if (it + 2 < KT) {
                issue_stage((it + 2) % GM_NSTAGE, (it + 2) * GM_BK);
                CP_WAIT(2);
            } else if (it + 1 < KT) {
                CP_WAIT(1);
            } else {
                CP_WAIT(0);
            }
            __syncthreads();

            const uint32_t stb = smb + (uint32_t)(it % GM_NSTAGE) * GM_STAGEB;

#pragma unroll
            for (int ks = 0; ks < GM_BK / 16; ks++) {
                const uint32_t kOff = (uint32_t)(ks * 32);
                uint32_t a[4][4];
#pragma unroll
                for (int mt = 0; mt < 4; mt++) {
                    uint32_t ra = stb + (uint32_t)((wm + mt * 16 + aRow) * GM_ROWB)
                                + kOff + aCol;
                    ldsm4(a[mt][0], a[mt][1], a[mt][2], a[mt][3], ra);
                }
                uint32_t b[4][2];
#pragma unroll
                for (int p = 0; p < 2; p++) {
                    uint32_t rb = stb + GM_BUFB
                                + (uint32_t)((wn + p * 16 + bRow) * GM_ROWB)
                                + kOff + bCol;
                    ldsm4(b[2*p][0], b[2*p][1], b[2*p+1][0], b[2*p+1][1], rb);
                }
#pragma unroll
                for (int nt = 0; nt < 4; nt++)
#pragma unroll
                    for (int mt = 0; mt < 4; mt++)
                        mma_f16(c[mt][nt], a[mt][0], a[mt][1], a[mt][2], a[mt][3],
                                b[nt][0], b[nt][1]);
            }
            __syncthreads();
        }
    }
};

// ---------------------------------------------------------------------------
// QKV GEMM with fused bias + RoPE + head split epilogue -> fp16 Q/K/V
// ---------------------------------------------------------------------------
__global__ __launch_bounds__(256, 2)
void gemm_qkv(const __half* __restrict__ A,
              const __half* __restrict__ B,
              const float* __restrict__ bias,
              const float* __restrict__ cosT,
              const float* __restrict__ sinT)
{
    extern __shared__ char sm[];
    GemmCore gc;
    gc.smb = smem_u32(sm);
    gc.tid = threadIdx.x;
    gc.wid = gc.tid >> 5;
    gc.lid = gc.tid & 31;
    gc.wm  = (gc.wid >> 2) * 64;
    gc.wn  = (gc.wid & 3) * 32;
    gc.m0  = blockIdx.y * 128;
    gc.n0  = blockIdx.x * 128;
    gc.K   = CH;
    gc.A = A; gc.B = B;

    float c[4][4][4];
#pragma unroll
    for (int i = 0; i < 4; i++)
#pragma unroll
        for (int j = 0; j < 4; j++)
#pragma unroll
            for (int q = 0; q < 4; q++) c[i][j][q] = 0.f;

    gc.run(c);

    const int gid = gc.lid >> 2;
    const int tig = gc.lid & 3;

#pragma unroll
    for (int mt = 0; mt < 4; mt++) {
#pragma unroll
        for (int nt = 0; nt < 4; nt++) {
            const int col = gc.n0 + gc.wn + nt * 8 + tig * 2;
            float2 b01 = *(const float2*)(bias + col);
            const int seg = col >> 10;
            const int cc  = col & 1023;
            const int h   = cc >> 6;
            const int d   = cc & 63;
            const int pr  = d >> 1;
            __half* Dst = (seg == 0) ? d_Q16 : (seg == 1) ? d_K16 : d_V16;
#pragma unroll
            for (int half_ = 0; half_ < 2; half_++) {
                const int row = gc.m0 + gc.wm + mt * 16 + gid + half_ * 8;
                const int t   = row & (SEQ - 1);
                const int b   = row >> 11;
                float e = c[mt][nt][half_ * 2 + 0] + b01.x;
                float o = c[mt][nt][half_ * 2 + 1] + b01.y;
                if (seg < 2) {
                    float cs = cosT[t * 32 + pr];
                    float sn = sinT[t * 32 + pr];
                    float re = e * cs - o * sn;
                    float ro = e * sn + o * cs;
                    e = re; o = ro;
                }
                size_t off = ((size_t)(b * NHEAD + h) * SEQ + t) * HDIM + d;
                *(uint32_t*)(Dst + off) = pack2h(e, o);
            }
        }
    }
}

// ---------------------------------------------------------------------------
// projection GEMM: fp32 output + bias
// ---------------------------------------------------------------------------
__global__ __launch_bounds__(256, 2)
void gemm_proj(const __half* __restrict__ A,
               const __half* __restrict__ B,
               const float* __restrict__ bias, float* __restrict__ C,
               int M, int N, int K)
{
    extern __shared__ char sm[];
    GemmCore gc;
    gc.smb = smem_u32(sm);
    gc.tid = threadIdx.x;
    gc.wid = gc.tid >> 5;
    gc.lid = gc.tid & 31;
    gc.wm  = (gc.wid >> 2) * 64;
    gc.wn  = (gc.wid & 3) * 32;
    gc.m0  = blockIdx.y * 128;
    gc.n0  = blockIdx.x * 128;
    gc.K   = K;
    gc.A = A; gc.B = B;

    float c[4][4][4];
#pragma unroll
    for (int i = 0; i < 4; i++)
#pragma unroll
        for (int j = 0; j < 4; j++)
#pragma unroll
            for (int q = 0; q < 4; q++) c[i][j][q] = 0.f;

    gc.run(c);

    const int gid = gc.lid >> 2;
    const int tig = gc.lid & 3;
#pragma unroll
    for (int mt = 0; mt < 4; mt++) {
#pragma unroll
        for (int nt = 0; nt < 4; nt++) {
            const int row = gc.m0 + gc.wm + mt * 16 + gid;
            const int col = gc.n0 + gc.wn + nt * 8 + tig * 2;
            float2 b01 = *(const float2*)(bias + col);
            float2 v0 = make_float2(c[mt][nt][0] + b01.x, c[mt][nt][1] + b01.y);
            float2 v1 = make_float2(c[mt][nt][2] + b01.x, c[mt][nt][3] + b01.y);
            *(float2*)(C + (size_t)row * N + col)       = v0;
            *(float2*)(C + (size_t)(row + 8) * N + col) = v1;
        }
    }
}

// ---------------------------------------------------------------------------
// fp32 -> fp16 convert
// ---------------------------------------------------------------------------
__global__ void convert_half(const float* __restrict__ X,
                             __half* __restrict__ Y, int n)
{
    int i = (blockIdx.x * blockDim.x + threadIdx.x) * 4;
    if (i >= n) return;
    float4 v = *(const float4*)(X + i);
    uint32_t p0 = pack2h(v.x, v.y);
    uint32_t p1 = pack2h(v.z, v.w);
    *(uint32_t*)(Y + i)     = p0;
    *(uint32_t*)(Y + i + 2) = p1;
}

// ---------------------------------------------------------------------------
// transpose: W[K,N] fp32 -> T[N,K] fp16
// ---------------------------------------------------------------------------
__global__ void transpose_half(const float* __restrict__ W,
                               __half* __restrict__ T, int K, int N)
{
    __shared__ float tile[32][33];
    const int n0 = blockIdx.x * 32;
    const int k0 = blockIdx.y * 32;
    const int tx = threadIdx.x;
    const int ty = threadIdx.y;
#pragma unroll
    for (int i = 0; i < 32; i += 8)
        tile[ty + i][tx] = W[(size_t)(k0 + ty + i) * N + n0 + tx];
    __syncthreads();
#pragma unroll
    for (int i = 0; i < 32; i += 8)
        T[(size_t)(n0 + ty + i) * K + k0 + tx] = __float2half(tile[tx][ty + i]);
}

// ---------------------------------------------------------------------------
// Flash attention (fp16 single-pass mma.sync)
// ---------------------------------------------------------------------------
#define FA_STRB 144
#define FA_TILEB (64 * FA_STRB)             // 9216
#define FA_KVSTAGE (2 * FA_TILEB)           // K + V
#define FA_SMEM_BYTES (FA_TILEB + 2 * FA_KVSTAGE)   // 46080

__global__ __launch_bounds__(128)
void flash_mma(const __half* __restrict__ Q,
               const __half* __restrict__ Kg,
               const __half* __restrict__ Vg,
               __half* __restrict__ Aout)
{
    extern __shared__ char smem[];
    const uint32_t smb = smem_u32(smem);
    const int tid = threadIdx.x;
    const int wid = tid >> 5;
    const int lid = tid & 31;
    const int g   = lid >> 2;
    const int t   = lid & 3;
    const int wq  = wid * 16;
    const int qt  = gridDim.x - 1 - blockIdx.x;
    const int bh  = blockIdx.y;
    const int q0  = qt * 64;

    const int aRow = lid & 15;
    const int aCol = (lid >> 4) << 4;
    const int bRow = (lid & 7) + ((lid & 16) >> 1);
    const int bCol = ((lid >> 3) & 1) << 4;
    const int vRow = (lid & 7) + ((lid >> 3) & 1) * 8;
    const int vColH = (lid >> 4) * 8;

    const size_t base = (size_t)bh * SEQ * HDIM;
    const __half* Qb = Q  + base;
    const __half* Kb = Kg + base;
    const __half* Vb = Vg + base;

    auto issue_kv = [&](int st, int kt) {
#pragma unroll
        for (int i = 0; i < 8; i++) {
            int id  = tid + i * 128;           // 0..1023
            int buf = id >> 9;                 // 0=K 1=V
            int cc  = id & 511;
            int r   = cc >> 3;
            int c8  = (cc & 7) * 8;
            uint32_t dst = smb + FA_TILEB + (uint32_t)st * FA_KVSTAGE
                         + (uint32_t)buf * FA_TILEB
                         + (uint32_t)(r * FA_STRB + c8 * 2);
            const __half* src = (buf == 0)
                ? Kb + (size_t)(kt + r) * HDIM + c8
                : Vb + (size_t)(kt + r) * HDIM + c8;
            CP_ASYNC16(dst, src);
        }
        CP_COMMIT();
    };

    issue_kv(0, 0);

#pragma unroll
    for (int i = 0; i < 4; i++) {
        int id = tid + i * 128;
        int r  = id >> 3;
        int c8 = (id & 7) * 8;
        uint4 v = *(const uint4*)(Qb + (size_t)(q0 + r) * HDIM + c8);
        *(uint4*)(smem + r * FA_STRB + c8 * 2) = v;
    }

    float m0 = -INFINITY, m1 = -INFINITY, l0 = 0.f, l1 = 0.f;
    float oc[8][4];
#pragma unroll
    for (int nf = 0; nf < 8; nf++)
#pragma unroll
        for (int cidx = 0; cidx < 4; cidx++) oc[nf][cidx] = 0.f;

    for (int jt = 0; jt <= qt; jt++) {
        if (jt < qt) {
            issue_kv((jt + 1) & 1, (jt + 1) * 64);
            CP_WAIT(1);
        } else {
            CP_WAIT(0);
        }
        __syncthreads();

        const uint32_t kvb = smb + FA_TILEB + (uint32_t)(jt & 1) * FA_KVSTAGE;

        // ---- S = Q @ K^T ----
        float sc[8][4];
#pragma unroll
        for (int nf = 0; nf < 8; nf++)
#pragma unroll
            for (int cidx = 0; cidx < 4; cidx++) sc[nf][cidx] = 0.f;

#pragma unroll
        for (int kc = 0; kc < 4; kc++) {
            const uint32_t kOff = (uint32_t)(kc * 32);
            uint32_t qf[4];
            uint32_t qa = smb + (uint32_t)((wq + aRow) * FA_STRB) + kOff + aCol;
            ldsm4(qf[0], qf[1], qf[2], qf[3], qa);
#pragma unroll
            for (int p = 0; p < 4; p++) {
                uint32_t ka = kvb + (uint32_t)((p * 16 + bRow) * FA_STRB)
                            + kOff + bCol;
                uint32_t k0_, k1_, k2_, k3_;
                ldsm4(k0_, k1_, k2_, k3_, ka);
                mma_f16(sc[2*p],   qf[0], qf[1], qf[2], qf[3], k0_, k1_);
                mma_f16(sc[2*p+1], qf[0], qf[1], qf[2], qf[3], k2_, k3_);
            }
        }

#pragma unroll
        for (int nf = 0; nf < 8; nf++)
#pragma unroll
            for (int cidx = 0; cidx < 4; cidx++) sc[nf][cidx] *= 0.125f;

        if (jt == qt) {
            const int qg0 = q0 + wq + g;
            const int qg1 = qg0 + 8;
#pragma unroll
            for (int nf = 0; nf < 8; nf++) {
                const int kb = q0 + nf * 8 + t * 2;
                if (kb     > qg0) sc[nf][0] = -INFINITY;
                if (kb + 1 > qg0) sc[nf][1] = -INFINITY;
                if (kb     > qg1) sc[nf][2] = -INFINITY;
                if (kb + 1 > qg1) sc[nf][3] = -INFINITY;
            }
        }

        // ---- online softmax ----
        float a0 = -INFINITY, a1 = -INFINITY;
#pragma unroll
        for (int nf = 0; nf < 8; nf++) {
            a0 = fmaxf(a0, fmaxf(sc[nf][0], sc[nf][1]));
            a1 = fmaxf(a1, fmaxf(sc[nf][2], sc[nf][3]));
        }
        a0 = fmaxf(a0, __shfl_xor_sync(0xffffffffu, a0, 1));
        a0 = fmaxf(a0, __shfl_xor_sync(0xffffffffu, a0, 2));
        a1 = fmaxf(a1, __shfl_xor_sync(0xffffffffu, a1, 1));
        a1 = fmaxf(a1, __shfl_xor_sync(0xffffffffu, a1, 2));

        float mn0 = fmaxf(m0, a0), mn1 = fmaxf(m1, a1);
        float cr0 = __expf(m0 - mn0), cr1 = __expf(m1 - mn1);
        float rs0 = 0.f, rs1 = 0.f;
#pragma unroll
        for (int nf = 0; nf < 8; nf++) {
            sc[nf][0] = __expf(sc[nf][0] - mn0);
            sc[nf][1] = __expf(sc[nf][1] - mn0);
            sc[nf][2] = __expf(sc[nf][2] - mn1);
            sc[nf][3] = __expf(sc[nf][3] - mn1);
            rs0 += sc[nf][0] + sc[nf][1];
            rs1 += sc[nf][2] + sc[nf][3];
        }
        rs0 += __shfl_xor_sync(0xffffffffu, rs0, 1);
        rs0 += __shfl_xor_sync(0xffffffffu, rs0, 2);
        rs1 += __shfl_xor_sync(0xffffffffu, rs1, 1);
        rs1 += __shfl_xor_sync(0xffffffffu, rs1, 2);
        l0 = l0 * cr0 + rs0;  m0 = mn0;
        l1 = l1 * cr1 + rs1;  m1 = mn1;
#pragma unroll
        for (int nf = 0; nf < 8; nf++) {
            oc[nf][0] *= cr0; oc[nf][1] *= cr0;
            oc[nf][2] *= cr1; oc[nf][3] *= cr1;
        }

        // ---- O += P @ V (V via ldmatrix.trans) ----
#pragma unroll
        for (int kc = 0; kc < 4; kc++) {
            uint32_t pa0 = pack2h(sc[2*kc][0],   sc[2*kc][1]);
            uint32_t pa1 = pack2h(sc[2*kc][2],   sc[2*kc][3]);
            uint32_t pa2 = pack2h(sc[2*kc+1][0], sc[2*kc+1][1]);
            uint32_t pa3 = pack2h(sc[2*kc+1][2], sc[2*kc+1][3]);
#pragma unroll
            for (int p = 0; p < 4; p++) {
                uint32_t va = kvb + FA_TILEB
                            + (uint32_t)((kc * 16 + vRow) * FA_STRB)
                            + (uint32_t)((p * 16 + vColH) * 2);
                uint32_t v0, v1, v2, v3;
                ldsm4t(v0, v1, v2, v3, va);
                mma_f16(oc[2*p],   pa0, pa1, pa2, pa3, v0, v1);
                mma_f16(oc[2*p+1], pa0, pa1, pa2, pa3, v2, v3);
            }
        }
        __syncthreads();
    }

    // ---- epilogue ----
    const int b = bh >> 4;
    const int h = bh & 15;
    const float inv0 = 1.f / l0;
    const float inv1 = 1.f / l1;
    const int row0 = b * SEQ + q0 + wq + g;
    const int row1 = row0 + 8;
#pragma unroll
    for (int nf = 0; nf < 8; nf++) {
        const int col = h * HDIM + nf * 8 + t * 2;
        *(uint32_t*)(Aout + (size_t)row0 * CH + col) =
            pack2h(oc[nf][0] * inv0, oc[nf][1] * inv0);
        *(uint32_t*)(Aout + (size_t)row1 * CH + col) =
            pack2h(oc[nf][2] * inv1, oc[nf][3] * inv1);
    }
}

// ---------------------------------------------------------------------------
extern "C" void kernel_launch(void* const* d_in, const int* in_sizes, int n_in,
                              void* d_out, int out_size)
{
    const float* x      = (const float*)d_in[0];
    const float* cosT   = (const float*)d_in[1];
    const float* sinT   = (const float*)d_in[2];
    const float* w_attn = (const float*)d_in[3];
    const float* b_attn = (const float*)d_in[4];
    const float* w_proj = (const float*)d_in[5];
    const float* b_proj = (const float*)d_in[6];
    float* out = (float*)d_out;

    __half *x16, *a16, *wa16, *wp16, *q16, *k16, *v16;
    cudaGetSymbolAddress((void**)&x16,  d_x16);
    cudaGetSymbolAddress((void**)&a16,  d_a16);
    cudaGetSymbolAddress((void**)&wa16, d_wa16T);
    cudaGetSymbolAddress((void**)&wp16, d_wp16T);
    cudaGetSymbolAddress((void**)&q16,  d_Q16);
    cudaGetSymbolAddress((void**)&k16,  d_K16);
    cudaGetSymbolAddress((void**)&v16,  d_V16);

    cudaFuncSetAttribute(gemm_qkv, cudaFuncAttributeMaxDynamicSharedMemorySize,
                         GM_SMEM_BYTES);
    cudaFuncSetAttribute(gemm_proj, cudaFuncAttributeMaxDynamicSharedMemorySize,
                         GM_SMEM_BYTES);
    cudaFuncSetAttribute(flash_mma, cudaFuncAttributeMaxDynamicSharedMemorySize,
                         FA_SMEM_BYTES);

    {
        int n = NROW * CH;
        convert_half<<<(n / 4 + 255) / 256, 256>>>(x, x16, n);
        transpose_half<<<dim3(3 * CH / 32, CH / 32), dim3(32, 8)>>>(
            w_attn, wa16, CH, 3 * CH);
        transpose_half<<<dim3(CH / 32, CH / 32), dim3(32, 8)>>>(
            w_proj, wp16, CH, CH);
    }

    // 1) QKV GEMM with fused RoPE/split epilogue
    gemm_qkv<<<dim3(3 * CH / 128, NROW / 128), 256, GM_SMEM_BYTES>>>(
        x16, wa16, b_attn, cosT, sinT);

    // 2) flash attention -> fp16 proj operand
    flash_mma<<<dim3(SEQ / 64, BATCH * NHEAD), 128, FA_SMEM_BYTES>>>(
        q16, k16, v16, a16);

    // 3) projection GEMM
    gemm_proj<<<dim3(CH / 128, NROW / 128), 256, GM_SMEM_BYTES>>>(
        a16, wp16, b_proj, out, NROW, CH, CH);
}